// round 11
// baseline (speedup 1.0000x reference)
#include <cuda_runtime.h>
#include <cuda_bf16.h>
#include <cstdint>

// ---------------- problem constants ----------------
static constexpr int NNODE = 10000;
static constexpr int NEDGE = 50000;
static constexpr int HID   = 128;
static constexpr int WTOT  = 3364;  // 2304 + 480 + 100 + 480
static constexpr int OFF2  = 2304;
static constexpr int OFF3  = 2784;
static constexpr int OFF4  = 2884;
static constexpr int TB    = 128;
static constexpr int NBLK  = (NEDGE + TB - 1) / TB;    // 391
static constexpr int NCHUNK = 27;
static constexpr int TILE_W = 128 * 64;                // words per bf16x2 tile (8192)

#define EPS_BN     1e-5f
#define INV_SQRT3  0.57735026918962576f
#define NORM01     0.13130643285972254f   /* 1/sqrt(58) */

// ---------------- mma.sync helper (Ampere-class HMMA, compiles for sm_103) ----------
__device__ __forceinline__ void mma16816(float* c, const uint32_t* a,
                                         uint32_t b0, uint32_t b1) {
  asm volatile(
      "mma.sync.aligned.m16n8k16.row.col.f32.bf16.bf16.f32 "
      "{%0,%1,%2,%3}, {%4,%5,%6,%7}, {%8,%9}, {%0,%1,%2,%3};"
      : "+f"(c[0]), "+f"(c[1]), "+f"(c[2]), "+f"(c[3])
      : "r"(a[0]), "r"(a[1]), "r"(a[2]), "r"(a[3]), "r"(b0), "r"(b1));
}

// smem tile: row-major, 64 k-words (bf16x2) per row, pitch 68 words (272 B),
// per-octet XOR swizzle on k-word index -> conflict-free fragment loads & builds.
__device__ __forceinline__ uint32_t toff(int row, int kp) {
  return (uint32_t)(row * 68 + (kp ^ ((row >> 3) & 3))) * 4u;
}
// global pre-swizzled compact tile (pitch 64 words), same word order per 16B group
__device__ __forceinline__ uint32_t gidx(int row, int kp) {
  return (uint32_t)(row * 64 + (kp ^ ((row >> 3) & 3)));
}

// bf16 hi/lo split
__device__ __forceinline__ void bsplit(float x, __nv_bfloat16& hi, __nv_bfloat16& lo) {
  hi = __float2bfloat16(x);
  lo = __float2bfloat16(x - __bfloat162float(hi));
}
__device__ __forceinline__ uint32_t pack2(__nv_bfloat16 a, __nv_bfloat16 b) {
  __nv_bfloat162 v; v.x = a; v.y = b;
  return *(uint32_t*)&v;
}

// cp.async helpers
__device__ __forceinline__ uint32_t smem_u32(const void* p) {
  uint32_t a;
  asm("{ .reg .u64 t; cvta.to.shared.u64 t, %1; cvt.u32.u64 %0, t; }" : "=r"(a) : "l"(p));
  return a;
}
__device__ __forceinline__ void cp16(uint32_t dst, const void* src) {
  asm volatile("cp.async.cg.shared.global [%0], [%1], 16;" :: "r"(dst), "l"(src));
}
__device__ __forceinline__ void cp_commit_wait_all() {
  asm volatile("cp.async.commit_group;");
  asm volatile("cp.async.wait_group 0;" ::: "memory");
}

// chunk schedule (shared by k_prep / k_fused)
__device__ __forceinline__ void chunk_params(int ci, int& type, int& jstart,
                                             int& cnt, int& rel) {
  if (ci < 4)       { type = 2; rel = ci * 120;        jstart = OFF2 + rel; cnt = 120; }
  else if (ci < 22) { type = 1; rel = (ci - 4) * 128;  jstart = rel;        cnt = 128; }
  else if (ci < 26) { type = 4; rel = (ci - 22) * 120; jstart = OFF4 + rel; cnt = 120; }
  else              { type = 3; rel = 0;               jstart = OFF3;       cnt = 100; }
}

// ---------------- scratch ----------------
__device__ uint32_t g_Ahi[(size_t)NBLK * TILE_W];       // relu(h) hi tiles, pre-swizzled
__device__ uint32_t g_Alo[(size_t)NBLK * TILE_W];
__device__ uint32_t g_W2hi[(size_t)NCHUNK * TILE_W];    // W2^T chunk tiles, pre-swizzled
__device__ uint32_t g_W2lo[(size_t)NCHUNK * TILE_W];
__device__ uint32_t g_W1hi[TILE_W];                     // W1^T tile
__device__ uint32_t g_W1lo[TILE_W];
__device__ float g_sum[(size_t)NNODE * 78];
__device__ float g_cnt[NNODE];
__device__ float g_stats[106];

// ---------------- K0: zero scratch ----------------
__global__ void k_zero() {
  int idx = blockIdx.x * blockDim.x + threadIdx.x;
  int stride = gridDim.x * blockDim.x;
  for (int i = idx; i < NNODE * 78; i += stride) g_sum[i] = 0.f;
  for (int i = idx; i < NNODE; i += stride) g_cnt[i] = 0.f;
  if (idx < 106) g_stats[idx] = 0.f;
}

// ---------------- Kp: pre-split W1 / W2 into pre-swizzled bf16 hi/lo tiles ----------
__global__ void k_prep(const float* __restrict__ W1, const float* __restrict__ W2) {
  int idx = blockIdx.x * blockDim.x + threadIdx.x;
  int stride = gridDim.x * blockDim.x;
  int total = NCHUNK * TILE_W + TILE_W;
  for (int i = idx; i < total; i += stride) {
    if (i < NCHUNK * TILE_W) {
      int ci = i / TILE_W;
      int r  = i - ci * TILE_W;
      int kp = r >> 7, j = r & 127;
      int type, jstart, cnt, rel;
      chunk_params(ci, type, jstart, cnt, rel);
      float x0 = 0.f, x1 = 0.f;
      if (j < cnt) {
        x0 = W2[(size_t)(2 * kp) * WTOT + jstart + j];
        x1 = W2[(size_t)(2 * kp + 1) * WTOT + jstart + j];
      }
      __nv_bfloat16 h0, l0, h1, l1;
      bsplit(x0, h0, l0); bsplit(x1, h1, l1);
      uint32_t o = (uint32_t)ci * TILE_W + gidx(j, kp);
      g_W2hi[o] = pack2(h0, h1);
      g_W2lo[o] = pack2(l0, l1);
    } else {
      int r = i - NCHUNK * TILE_W;
      int kp = r >> 7, c = r & 127;
      float x0 = W1[(size_t)(2 * kp) * 128 + c];
      float x1 = W1[(size_t)(2 * kp + 1) * 128 + c];
      __nv_bfloat16 h0, l0, h1, l1;
      bsplit(x0, h0, l0); bsplit(x1, h1, l1);
      uint32_t o = gidx(c, kp);
      g_W1hi[o] = pack2(h0, h1);
      g_W1lo[o] = pack2(l0, l1);
    }
  }
}

// ---------------- K1: HMMA h = relu(edge_attr @ W1 + b1) -> bf16 hi/lo A tiles ------
static constexpr int T68B   = 128 * 68 * 4;             // 34816 bytes per smem tile
static constexpr int K1_SMEM = 4 * T68B;                // A_hi, A_lo, B_hi, B_lo

__global__ __launch_bounds__(512) void k_gemm1(const float* __restrict__ A,
                                               const float* __restrict__ b1) {
  extern __shared__ char smem[];
  char* sAhi = smem;
  char* sAlo = smem + T68B;
  char* sBhi = smem + 2 * T68B;
  char* sBlo = smem + 3 * T68B;
  uint32_t sb = smem_u32(smem);

  int tid = threadIdx.x;
  int wid = tid >> 5, lane = tid & 31;
  int blk = blockIdx.x;
  int e0 = blk * TB;

  // B tiles: straight cp.async copy of pre-split W1 (16B groups, swizzle identity)
  for (int i = tid; i < 2048; i += 512) {
    int r = i >> 4, grp = i & 15;
    uint32_t d = (uint32_t)(r * 272 + grp * 16);
    cp16(sb + 2 * T68B + d, (const char*)g_W1hi + i * 16);
    cp16(sb + 3 * T68B + d, (const char*)g_W1lo + i * 16);
  }

  // A tiles: load edge_attr fp32 (coalesced), split, store swizzled
  for (int i = tid; i < 128 * 64; i += 512) {
    int e = i >> 6, kp = i & 63;
    float2 x = make_float2(0.f, 0.f);
    if (e0 + e < NEDGE) x = *(const float2*)&A[(size_t)(e0 + e) * 128 + 2 * kp];
    __nv_bfloat16 h0, l0, h1, l1;
    bsplit(x.x, h0, l0); bsplit(x.y, h1, l1);
    uint32_t off = toff(e, kp);
    *(uint32_t*)(sAhi + off) = pack2(h0, h1);
    *(uint32_t*)(sAlo + off) = pack2(l0, l1);
  }
  cp_commit_wait_all();
  __syncthreads();

  int m0 = (wid >> 2) * 32, n0 = (wid & 3) * 32;
  int g = lane >> 2, t = lane & 3;

  float acc[2][4][4];
#pragma unroll
  for (int mi = 0; mi < 2; ++mi)
#pragma unroll
    for (int ni = 0; ni < 4; ++ni)
#pragma unroll
      for (int r = 0; r < 4; ++r) acc[mi][ni][r] = 0.f;

#pragma unroll
  for (int pass = 0; pass < 3; ++pass) {
    const char* pA = (pass == 2) ? sAlo : sAhi;
    const char* pB = (pass == 1) ? sBlo : sBhi;
#pragma unroll
    for (int ks = 0; ks < 8; ++ks) {
      int kp0 = ks * 8 + t;
      uint32_t a[2][4];
#pragma unroll
      for (int mi = 0; mi < 2; ++mi) {
        int row = m0 + mi * 16 + g;
        a[mi][0] = *(const uint32_t*)(pA + toff(row,     kp0));
        a[mi][1] = *(const uint32_t*)(pA + toff(row + 8, kp0));
        a[mi][2] = *(const uint32_t*)(pA + toff(row,     kp0 + 4));
        a[mi][3] = *(const uint32_t*)(pA + toff(row + 8, kp0 + 4));
      }
#pragma unroll
      for (int ni = 0; ni < 4; ++ni) {
        int n = n0 + ni * 8 + g;
        uint32_t b0 = *(const uint32_t*)(pB + toff(n, kp0));
        uint32_t b1 = *(const uint32_t*)(pB + toff(n, kp0 + 4));
        mma16816(acc[0][ni], a[0], b0, b1);
        mma16816(acc[1][ni], a[1], b0, b1);
      }
    }
  }

  // epilogue: +bias, relu, split, store pre-swizzled A tiles (no staging)
  uint32_t* dsthi = g_Ahi + (size_t)blk * TILE_W;
  uint32_t* dstlo = g_Alo + (size_t)blk * TILE_W;
#pragma unroll
  for (int ni = 0; ni < 4; ++ni) {
    int c0 = n0 + ni * 8 + 2 * t;
    int kp = c0 >> 1;
    float bx = b1[c0], by = b1[c0 + 1];
#pragma unroll
    for (int mi = 0; mi < 2; ++mi) {
      int row = m0 + mi * 16 + g;
      float v0 = fmaxf(acc[mi][ni][0] + bx, 0.f);
      float v1 = fmaxf(acc[mi][ni][1] + by, 0.f);
      float v2 = fmaxf(acc[mi][ni][2] + bx, 0.f);
      float v3 = fmaxf(acc[mi][ni][3] + by, 0.f);
      __nv_bfloat16 h0, l0, h1, l1;
      bsplit(v0, h0, l0); bsplit(v1, h1, l1);
      dsthi[gidx(row, kp)] = pack2(h0, h1);
      dstlo[gidx(row, kp)] = pack2(l0, l1);
      bsplit(v2, h0, l0); bsplit(v3, h1, l1);
      dsthi[gidx(row + 8, kp)] = pack2(h0, h1);
      dstlo[gidx(row + 8, kp)] = pack2(l0, l1);
    }
  }
}

// ---------------- K2: fused HMMA GEMM2 (bf16x3) + tensor product + scatter --------
static constexpr int SM_AHI  = 0;
static constexpr int SM_ALO  = T68B;                    // 34816
static constexpr int SM_BHI  = 2 * T68B;                // 69632  (also sC staging)
static constexpr int SM_BLO  = 3 * T68B;                // 104448
static constexpr int SM_TPF  = 4 * T68B;                // 139264
static constexpr int FS_S    = SM_TPF / 4;              // 128*48
static constexpr int FS_DOT  = FS_S + 128 * 48;
static constexpr int FS_VIN  = FS_DOT + 128 * 10;
static constexpr int FS_SH   = FS_VIN + 128 * 30;
static constexpr int FS_AC0  = FS_SH + 128 * 4;
static constexpr int FS_YA   = FS_AC0 + 128 * 48;
static constexpr int FS_YB   = FS_YA + 128 * 10;
static constexpr int SM_BIAS = (FS_YB + 128 * 30) * 4;  // 231424
static constexpr int K2_SMEM = SM_BIAS + 512;           // 231936

__global__ __launch_bounds__(512) void k_fused(const int* __restrict__ eidx,
                                               const float* __restrict__ node_attr,
                                               const float* __restrict__ edge_sh,
                                               const float* __restrict__ b2) {
  extern __shared__ char smem[];
  float* smf   = (float*)smem;
  float* sC    = (float*)(smem + SM_BHI);   // C staging, pitch 132 (overlays B)
  float* sS    = smf + FS_S;
  float* sDot  = smf + FS_DOT;
  float* sVin  = smf + FS_VIN;
  float* sSh   = smf + FS_SH;
  float* sAc0  = smf + FS_AC0;
  float* sYa   = smf + FS_YA;
  float* sYb   = smf + FS_YB;
  float* sBias = (float*)(smem + SM_BIAS);
  uint32_t sb = smem_u32(smem);

  int tid = threadIdx.x;
  int wid = tid >> 5, lane = tid & 31;
  int blk = blockIdx.x;
  int e0 = blk * TB;

  // ---- A tiles: straight cp.async copy of pre-split h tiles ----
  {
    const char* srchi = (const char*)(g_Ahi + (size_t)blk * TILE_W);
    const char* srclo = (const char*)(g_Alo + (size_t)blk * TILE_W);
    for (int i = tid; i < 2048; i += 512) {
      int r = i >> 4, grp = i & 15;
      uint32_t d = (uint32_t)(r * 272 + grp * 16);
      cp16(sb + SM_AHI + d, srchi + i * 16);
      cp16(sb + SM_ALO + d, srclo + i * 16);
    }
  }

  // zero accumulators (contiguous sAc0, sYa, sYb)
  for (int idx = tid; idx < 128 * (48 + 10 + 30); idx += 512) sAc0[idx] = 0.f;

  int e_ = tid >> 2, q = tid & 3;   // 4 owner threads per edge

  // left vectors
  {
    int eg = e0 + e_;
    if (eg < NEDGE) {
      int dst = eidx[NEDGE + eg];
      const float* x = node_attr + (size_t)dst * 78;
      for (int u = q * 12; u < q * 12 + 12; ++u) sS[e_ * 48 + u] = x[u];
      for (int m = q; m < 30; m += 4) sVin[e_ * 30 + m] = x[48 + m];
      if (q == 0)
        for (int i = 0; i < 4; ++i) sSh[e_ * 4 + i] = edge_sh[(size_t)eg * 4 + i];
    }
  }
  __syncthreads();
  {
    float s1 = sSh[e_ * 4 + 1], s2 = sSh[e_ * 4 + 2], s3 = sSh[e_ * 4 + 3];
    for (int u = q; u < 10; u += 4)
      sDot[e_ * 10 + u] = (sVin[e_ * 30 + u * 3] * s1 + sVin[e_ * 30 + u * 3 + 1] * s2 +
                           sVin[e_ * 30 + u * 3 + 2] * s3) * INV_SQRT3;
  }

  int m0 = (wid >> 2) * 32, n0 = (wid & 3) * 32;
  int g = lane >> 2, t = lane & 3;

  for (int ci = 0; ci < NCHUNK; ++ci) {
    int type, jstart, cnt, rel;
    chunk_params(ci, type, jstart, cnt, rel);

    __syncthreads();   // prior epilogue done with sC before overwriting B region

    // ---- B tiles: straight cp.async copy of pre-split W2 chunk ----
    {
      const char* srchi = (const char*)(g_W2hi + (size_t)ci * TILE_W);
      const char* srclo = (const char*)(g_W2lo + (size_t)ci * TILE_W);
      for (int i = tid; i < 2048; i += 512) {
        int r = i >> 4, grp = i & 15;
        uint32_t d = (uint32_t)(r * 272 + grp * 16);
        cp16(sb + SM_BHI + d, srchi + i * 16);
        cp16(sb + SM_BLO + d, srclo + i * 16);
      }
    }
    if (tid < 128) sBias[tid] = (tid < cnt) ? b2[jstart + tid] : 0.f;
    cp_commit_wait_all();
    __syncthreads();   // B tiles (+A on ci==0) + bias ready

    // ---- 3-pass HMMA: acc = Ah*Bh + Ah*Bl + Al*Bh (fp32 accum in regs) ----
    float acc[2][4][4];
#pragma unroll
    for (int mi = 0; mi < 2; ++mi)
#pragma unroll
      for (int ni = 0; ni < 4; ++ni)
#pragma unroll
        for (int r = 0; r < 4; ++r) acc[mi][ni][r] = 0.f;

#pragma unroll
    for (int pass = 0; pass < 3; ++pass) {
      const char* pA = smem + ((pass == 2) ? SM_ALO : SM_AHI);
      const char* pB = smem + ((pass == 1) ? SM_BLO : SM_BHI);
#pragma unroll
      for (int ks = 0; ks < 8; ++ks) {
        int kp0 = ks * 8 + t;
        uint32_t a[2][4];
#pragma unroll
        for (int mi = 0; mi < 2; ++mi) {
          int row = m0 + mi * 16 + g;
          a[mi][0] = *(const uint32_t*)(pA + toff(row,     kp0));
          a[mi][1] = *(const uint32_t*)(pA + toff(row + 8, kp0));
          a[mi][2] = *(const uint32_t*)(pA + toff(row,     kp0 + 4));
          a[mi][3] = *(const uint32_t*)(pA + toff(row + 8, kp0 + 4));
        }
#pragma unroll
        for (int ni = 0; ni < 4; ++ni) {
          int n = n0 + ni * 8 + g;
          uint32_t b0 = *(const uint32_t*)(pB + toff(n, kp0));
          uint32_t b1 = *(const uint32_t*)(pB + toff(n, kp0 + 4));
          mma16816(acc[0][ni], a[0], b0, b1);
          mma16816(acc[1][ni], a[1], b0, b1);
        }
      }
    }
    __syncthreads();   // all MMA reads of sB done before sC overwrite

    // ---- C fragments + bias -> sC staging (pitch 132) ----
#pragma unroll
    for (int mi = 0; mi < 2; ++mi) {
      int row = m0 + mi * 16 + g;
#pragma unroll
      for (int ni = 0; ni < 4; ++ni) {
        int col = n0 + ni * 8 + 2 * t;
        float bx = sBias[col], by = sBias[col + 1];
        *(float2*)&sC[row * 132 + col] =
            make_float2(acc[mi][ni][0] + bx, acc[mi][ni][1] + by);
        *(float2*)&sC[(row + 8) * 132 + col] =
            make_float2(acc[mi][ni][2] + bx, acc[mi][ni][3] + by);
      }
    }
    __syncthreads();   // sC complete

    // ---- ownership-partitioned TP epilogue (4 threads per edge) ----
    if (type == 1 || type == 4) {
      const float* mult = (type == 1) ? (sS + e_ * 48) : (sDot + e_ * 10);
      int umax = (type == 1) ? 47 : 9;
      const float* Cs = sC + e_ * 132 - rel;
#pragma unroll 4
      for (int vv = 0; vv < 12; ++vv) {
        int v = q * 12 + vv;
        int d = rel - v;
        int u0 = d > 0 ? (d + 47) / 48 : 0;
        int u1 = (rel + cnt - 1 - v) / 48; if (u1 > umax) u1 = umax;
        float p = 0.f;
        for (int u = u0; u <= u1; ++u) p = fmaf(Cs[u * 48 + v], mult[u], p);
        sAc0[e_ * 48 + v] += p;
      }
    } else if (type == 2) {
      const float* Cs = sC + e_ * 132 - rel;
      for (int v = q; v < 10; v += 4) {
        int d = rel - v;
        int u0 = d > 0 ? (d + 9) / 10 : 0;
        int u1 = (rel + cnt - 1 - v) / 10; if (u1 > 47) u1 = 47;
        float p = 0.f;
        for (int u = u0; u <= u1; ++u) p = fmaf(Cs[u * 10 + v], sS[e_ * 48 + u], p);
        sYa[e_ * 10 + v] += p;
      }
    } else {  // w3
      const float* Cs = sC + e_ * 132;
      for (int v = q; v < 10; v += 4) {
        float y0 = 0.f, y1 = 0.f, y2 = 0.f;
#pragma unroll
        for (int u = 0; u < 10; ++u) {
          float wv = Cs[u * 10 + v];
          y0 = fmaf(wv, sVin[e_ * 30 + u * 3 + 0], y0);
          y1 = fmaf(wv, sVin[e_ * 30 + u * 3 + 1], y1);
          y2 = fmaf(wv, sVin[e_ * 30 + u * 3 + 2], y2);
        }
        sYb[e_ * 30 + v * 3 + 0] += y0;
        sYb[e_ * 30 + v * 3 + 1] += y1;
        sYb[e_ * 30 + v * 3 + 2] += y2;
      }
    }

    if (ci == 3) {  // w2 phase done -> scale s by sh0 for the w1 phase
      __syncthreads();
      float s0 = sSh[e_ * 4 + 0];
      for (int vv = 0; vv < 12; ++vv) sS[e_ * 48 + q * 12 + vv] *= s0;
    }
  }
  __syncthreads();

  // ---- final per-edge output + scatter to node sums ----
  {
    int eg = e0 + e_;
    if (eg < NEDGE) {
      int src = eidx[eg];
      float s0 = sSh[e_ * 4], s1 = sSh[e_ * 4 + 1], s2 = sSh[e_ * 4 + 2], s3 = sSh[e_ * 4 + 3];
      float* dp = g_sum + (size_t)src * 78;
      for (int vv = 0; vv < 12; ++vv) {
        int v = q * 12 + vv;
        atomicAdd(&dp[v], sAc0[e_ * 48 + v] * NORM01);
      }
      for (int v = q; v < 10; v += 4) {
        float ya = sYa[e_ * 10 + v];
        atomicAdd(&dp[48 + v * 3 + 0], (ya * s1 + sYb[e_ * 30 + v * 3 + 0] * s0) * NORM01);
        atomicAdd(&dp[48 + v * 3 + 1], (ya * s2 + sYb[e_ * 30 + v * 3 + 1] * s0) * NORM01);
        atomicAdd(&dp[48 + v * 3 + 2], (ya * s3 + sYb[e_ * 30 + v * 3 + 2] * s0) * NORM01);
      }
      if (q == 0) atomicAdd(&g_cnt[src], 1.f);
    }
  }
}

// ---------------- K3: node finalize (mean + residual) + BN statistics ----------------
__global__ __launch_bounds__(256) void k_node(const float* __restrict__ node_attr,
                                              float* __restrict__ dout) {
  __shared__ float sP[106];
  int tid = threadIdx.x;
  if (tid < 106) sP[tid] = 0.f;
  __syncthreads();

  int n = blockIdx.x * blockDim.x + tid;
  bool valid = n < NNODE;
  float inv = 1.f;
  if (valid) inv = 1.f / fmaxf(g_cnt[n], 1.f);
  const float* srow  = g_sum + (valid ? (size_t)n * 78 : 0);
  const float* narow = node_attr + (valid ? (size_t)n * 78 : 0);

  for (int v = 0; v < 48; ++v) {
    float val = 0.f;
    if (valid) { val = srow[v] * inv + narow[v]; dout[(size_t)n * 78 + v] = val; }
    float s = val, qq = val * val;
#pragma unroll
    for (int o = 16; o; o >>= 1) {
      s += __shfl_xor_sync(0xffffffffu, s, o);
      qq += __shfl_xor_sync(0xffffffffu, qq, o);
    }
    if ((tid & 31) == 0) { atomicAdd(&sP[v], s); atomicAdd(&sP[48 + v], qq); }
  }
  for (int u = 0; u < 10; ++u) {
    float qq = 0.f;
    for (int i = 0; i < 3; ++i) {
      float val = 0.f;
      int c = 48 + u * 3 + i;
      if (valid) { val = srow[c] * inv + narow[c]; dout[(size_t)n * 78 + c] = val; }
      qq += val * val;
    }
#pragma unroll
    for (int o = 16; o; o >>= 1) qq += __shfl_xor_sync(0xffffffffu, qq, o);
    if ((tid & 31) == 0) atomicAdd(&sP[96 + u], qq);
  }
  __syncthreads();
  if (tid < 106) atomicAdd(&g_stats[tid], sP[tid]);
}

// ---------------- K4: apply batch norm in place ----------------
__global__ void k_bn(const float* __restrict__ bnw, const float* __restrict__ bnb,
                     float* __restrict__ dout) {
  int idx = blockIdx.x * blockDim.x + threadIdx.x;
  if (idx >= NNODE * 78) return;
  int c = idx % 78;
  float x = dout[idx];
  if (c < 48) {
    float mean = g_stats[c] * (1.f / NNODE);
    float var  = g_stats[48 + c] * (1.f / NNODE) - mean * mean;
    dout[idx] = (x - mean) * rsqrtf(var + EPS_BN) * bnw[c] + bnb[c];
  } else {
    int u = (c - 48) / 3;
    float vn = g_stats[96 + u] * (1.f / (3.f * NNODE));
    dout[idx] = x * rsqrtf(vn + EPS_BN) * bnw[48 + u];
  }
}

// ---------------- launch ----------------
extern "C" void kernel_launch(void* const* d_in, const int* in_sizes, int n_in,
                              void* d_out, int out_size) {
  const float* node_attr  = (const float*)d_in[0];
  const int*   edge_index = (const int*)d_in[1];
  const float* edge_attr  = (const float*)d_in[2];
  const float* edge_sh    = (const float*)d_in[3];
  const float* fc_w1      = (const float*)d_in[4];
  const float* fc_b1      = (const float*)d_in[5];
  const float* fc_w2      = (const float*)d_in[6];
  const float* fc_b2      = (const float*)d_in[7];
  const float* bn_w       = (const float*)d_in[8];
  const float* bn_b       = (const float*)d_in[9];
  float* out = (float*)d_out;

  cudaFuncSetAttribute(k_gemm1, cudaFuncAttributeMaxDynamicSharedMemorySize, K1_SMEM);
  cudaFuncSetAttribute(k_fused, cudaFuncAttributeMaxDynamicSharedMemorySize, K2_SMEM);

  k_zero<<<256, 256>>>();
  k_prep<<<432, 512>>>(fc_w1, fc_w2);
  k_gemm1<<<NBLK, 512, K1_SMEM>>>(edge_attr, fc_b1);
  k_fused<<<NBLK, 512, K2_SMEM>>>(edge_index, node_attr, edge_sh, fc_b2);
  k_node<<<(NNODE + 255) / 256, 256>>>(node_attr, out);
  k_bn<<<(NNODE * 78 + 255) / 256, 256>>>(bn_w, bn_b, out);
}

// round 12
// speedup vs baseline: 1.3211x; 1.3211x over previous
#include <cuda_runtime.h>
#include <cuda_bf16.h>
#include <cstdint>

// ---------------- problem constants ----------------
static constexpr int NNODE = 10000;
static constexpr int NEDGE = 50000;
static constexpr int HID   = 128;
static constexpr int WTOT  = 3364;  // 2304 + 480 + 100 + 480
static constexpr int OFF2  = 2304;
static constexpr int OFF3  = 2784;
static constexpr int OFF4  = 2884;
static constexpr int TB    = 128;
static constexpr int NBLK  = (NEDGE + TB - 1) / TB;    // 391
static constexpr int NCHUNK = 27;
static constexpr int TILE_W = 128 * 64;                // words per bf16x2 tile (8192)

#define EPS_BN     1e-5f
#define INV_SQRT3  0.57735026918962576f
#define NORM01     0.13130643285972254f   /* 1/sqrt(58) */

// ---------------- mma.sync / ldmatrix helpers (compile for sm_103) ----------
__device__ __forceinline__ void mma16816(float* c, const uint32_t* a,
                                         uint32_t b0, uint32_t b1) {
  asm volatile(
      "mma.sync.aligned.m16n8k16.row.col.f32.bf16.bf16.f32 "
      "{%0,%1,%2,%3}, {%4,%5,%6,%7}, {%8,%9}, {%0,%1,%2,%3};"
      : "+f"(c[0]), "+f"(c[1]), "+f"(c[2]), "+f"(c[3])
      : "r"(a[0]), "r"(a[1]), "r"(a[2]), "r"(a[3]), "r"(b0), "r"(b1));
}
__device__ __forceinline__ void ldsm4(uint32_t& r0, uint32_t& r1, uint32_t& r2,
                                      uint32_t& r3, uint32_t addr) {
  asm volatile("ldmatrix.sync.aligned.m8n8.x4.shared.b16 {%0,%1,%2,%3}, [%4];"
               : "=r"(r0), "=r"(r1), "=r"(r2), "=r"(r3) : "r"(addr));
}

// smem tile: row-major, 64 k-words (bf16x2) per row, pitch 68 words (272 B).
// NO swizzle: pitch 68 => 4-bank shift per row, so 8-row x 16B ldmatrix reads
// and 16-threads-per-row 16B builds are both conflict-free.
__device__ __forceinline__ uint32_t toff(int row, int kp) {
  return (uint32_t)(row * 68 + kp) * 4u;
}
// global compact tile (pitch 64 words), same 16B-group order as smem rows
__device__ __forceinline__ uint32_t gidx(int row, int kp) {
  return (uint32_t)(row * 64 + kp);
}

// bf16 hi/lo split
__device__ __forceinline__ void bsplit(float x, __nv_bfloat16& hi, __nv_bfloat16& lo) {
  hi = __float2bfloat16(x);
  lo = __float2bfloat16(x - __bfloat162float(hi));
}
__device__ __forceinline__ uint32_t pack2(__nv_bfloat16 a, __nv_bfloat16 b) {
  __nv_bfloat162 v; v.x = a; v.y = b;
  return *(uint32_t*)&v;
}

// cp.async helpers
__device__ __forceinline__ uint32_t smem_u32(const void* p) {
  uint32_t a;
  asm("{ .reg .u64 t; cvta.to.shared.u64 t, %1; cvt.u32.u64 %0, t; }" : "=r"(a) : "l"(p));
  return a;
}
__device__ __forceinline__ void cp16(uint32_t dst, const void* src) {
  asm volatile("cp.async.cg.shared.global [%0], [%1], 16;" :: "r"(dst), "l"(src));
}
__device__ __forceinline__ void cp_commit_wait_all() {
  asm volatile("cp.async.commit_group;");
  asm volatile("cp.async.wait_group 0;" ::: "memory");
}

// chunk schedule (shared by k_prep / k_fused)
__device__ __forceinline__ void chunk_params(int ci, int& type, int& jstart,
                                             int& cnt, int& rel) {
  if (ci < 4)       { type = 2; rel = ci * 120;        jstart = OFF2 + rel; cnt = 120; }
  else if (ci < 22) { type = 1; rel = (ci - 4) * 128;  jstart = rel;        cnt = 128; }
  else if (ci < 26) { type = 4; rel = (ci - 22) * 120; jstart = OFF4 + rel; cnt = 120; }
  else              { type = 3; rel = 0;               jstart = OFF3;       cnt = 100; }
}

// ---------------- scratch ----------------
__device__ uint32_t g_Ahi[(size_t)NBLK * TILE_W];       // relu(h) hi tiles, compact
__device__ uint32_t g_Alo[(size_t)NBLK * TILE_W];
__device__ uint32_t g_W2hi[(size_t)NCHUNK * TILE_W];    // W2^T chunk tiles, compact
__device__ uint32_t g_W2lo[(size_t)NCHUNK * TILE_W];
__device__ uint32_t g_W1hi[TILE_W];                     // W1^T tile
__device__ uint32_t g_W1lo[TILE_W];
__device__ float g_sum[(size_t)NNODE * 78];
__device__ float g_cnt[NNODE];
__device__ float g_stats[106];

// ---------------- K0: zero scratch ----------------
__global__ void k_zero() {
  int idx = blockIdx.x * blockDim.x + threadIdx.x;
  int stride = gridDim.x * blockDim.x;
  for (int i = idx; i < NNODE * 78; i += stride) g_sum[i] = 0.f;
  for (int i = idx; i < NNODE; i += stride) g_cnt[i] = 0.f;
  if (idx < 106) g_stats[idx] = 0.f;
}

// ---------------- Kp: pre-split W1 / W2 into compact bf16 hi/lo tiles ----------
__global__ void k_prep(const float* __restrict__ W1, const float* __restrict__ W2) {
  int idx = blockIdx.x * blockDim.x + threadIdx.x;
  int stride = gridDim.x * blockDim.x;
  int total = NCHUNK * TILE_W + TILE_W;
  for (int i = idx; i < total; i += stride) {
    if (i < NCHUNK * TILE_W) {
      int ci = i / TILE_W;
      int r  = i - ci * TILE_W;
      int j = r >> 6, kp = r & 63;     // output-linear: coalesced writes
      int type, jstart, cnt, rel;
      chunk_params(ci, type, jstart, cnt, rel);
      float x0 = 0.f, x1 = 0.f;
      if (j < cnt) {
        x0 = W2[(size_t)(2 * kp) * WTOT + jstart + j];
        x1 = W2[(size_t)(2 * kp + 1) * WTOT + jstart + j];
      }
      __nv_bfloat16 h0, l0, h1, l1;
      bsplit(x0, h0, l0); bsplit(x1, h1, l1);
      uint32_t o = (uint32_t)ci * TILE_W + gidx(j, kp);
      g_W2hi[o] = pack2(h0, h1);
      g_W2lo[o] = pack2(l0, l1);
    } else {
      int r = i - NCHUNK * TILE_W;
      int c = r >> 6, kp = r & 63;
      float x0 = W1[(size_t)(2 * kp) * 128 + c];
      float x1 = W1[(size_t)(2 * kp + 1) * 128 + c];
      __nv_bfloat16 h0, l0, h1, l1;
      bsplit(x0, h0, l0); bsplit(x1, h1, l1);
      uint32_t o = gidx(c, kp);
      g_W1hi[o] = pack2(h0, h1);
      g_W1lo[o] = pack2(l0, l1);
    }
  }
}

// ---------------- K1: HMMA h = relu(edge_attr @ W1 + b1) -> bf16 hi/lo A tiles ------
static constexpr int T68B   = 128 * 68 * 4;             // 34816 bytes per smem tile
static constexpr int K1_SMEM = 4 * T68B;                // A_hi, A_lo, B_hi, B_lo

__global__ __launch_bounds__(512) void k_gemm1(const float* __restrict__ A,
                                               const float* __restrict__ b1) {
  extern __shared__ char smem[];
  char* sAhi = smem;
  char* sAlo = smem + T68B;
  uint32_t sb = smem_u32(smem);

  int tid = threadIdx.x;
  int wid = tid >> 5, lane = tid & 31;
  int blk = blockIdx.x;
  int e0 = blk * TB;

  // B tiles: cp.async copy of pre-split W1 (16B groups)
  for (int i = tid; i < 2048; i += 512) {
    int r = i >> 4, grp = i & 15;
    uint32_t d = (uint32_t)(r * 272 + grp * 16);
    cp16(sb + 2 * T68B + d, (const char*)g_W1hi + i * 16);
    cp16(sb + 3 * T68B + d, (const char*)g_W1lo + i * 16);
  }

  // A tiles: load edge_attr fp32 (coalesced), split, store pitch-68
  for (int i = tid; i < 128 * 64; i += 512) {
    int e = i >> 6, kp = i & 63;
    float2 x = make_float2(0.f, 0.f);
    if (e0 + e < NEDGE) x = *(const float2*)&A[(size_t)(e0 + e) * 128 + 2 * kp];
    __nv_bfloat16 h0, l0, h1, l1;
    bsplit(x.x, h0, l0); bsplit(x.y, h1, l1);
    uint32_t off = toff(e, kp);
    *(uint32_t*)(sAhi + off) = pack2(h0, h1);
    *(uint32_t*)(sAlo + off) = pack2(l0, l1);
  }
  cp_commit_wait_all();
  __syncthreads();

  int m0 = (wid >> 2) * 32, n0 = (wid & 3) * 32;
  int g = lane >> 2, t = lane & 3;
  int lane15 = lane & 15;
  int khalf4 = (lane >> 4) << 2;   // 0 or 4 (k-word offset for ldmatrix halves)

  float acc[2][4][4];
#pragma unroll
  for (int mi = 0; mi < 2; ++mi)
#pragma unroll
    for (int ni = 0; ni < 4; ++ni)
#pragma unroll
      for (int r = 0; r < 4; ++r) acc[mi][ni][r] = 0.f;

#pragma unroll
  for (int pass = 0; pass < 3; ++pass) {
    uint32_t pa = sb + ((pass == 2) ? T68B : 0);
    uint32_t pb = sb + ((pass == 1) ? 3 * T68B : 2 * T68B);
    uint32_t aAd0 = pa + toff(m0 + lane15, khalf4);
    uint32_t aAd1 = aAd0 + 16 * 272;
    uint32_t bAd0 = pb + toff(n0 + lane15, khalf4);
    uint32_t bAd1 = bAd0 + 16 * 272;
#pragma unroll
    for (int ks = 0; ks < 8; ++ks) {
      uint32_t ko = (uint32_t)ks * 32;
      uint32_t a0[4], a1[4], b00, b01, b02, b03, b10, b11, b12, b13;
      ldsm4(a0[0], a0[1], a0[2], a0[3], aAd0 + ko);
      ldsm4(a1[0], a1[1], a1[2], a1[3], aAd1 + ko);
      ldsm4(b00, b01, b02, b03, bAd0 + ko);
      ldsm4(b10, b11, b12, b13, bAd1 + ko);
      mma16816(acc[0][0], a0, b00, b02);
      mma16816(acc[0][1], a0, b01, b03);
      mma16816(acc[0][2], a0, b10, b12);
      mma16816(acc[0][3], a0, b11, b13);
      mma16816(acc[1][0], a1, b00, b02);
      mma16816(acc[1][1], a1, b01, b03);
      mma16816(acc[1][2], a1, b10, b12);
      mma16816(acc[1][3], a1, b11, b13);
    }
  }
  __syncthreads();   // done reading A tiles; reuse sAhi/sAlo as export staging

  // epilogue: +bias, relu, split -> smem (pitch 68), then coalesced export
#pragma unroll
  for (int ni = 0; ni < 4; ++ni) {
    int c0 = n0 + ni * 8 + 2 * t;
    int kp = c0 >> 1;
    float bx = b1[c0], by = b1[c0 + 1];
#pragma unroll
    for (int mi = 0; mi < 2; ++mi) {
      int row = m0 + mi * 16 + g;
      float v0 = fmaxf(acc[mi][ni][0] + bx, 0.f);
      float v1 = fmaxf(acc[mi][ni][1] + by, 0.f);
      float v2 = fmaxf(acc[mi][ni][2] + bx, 0.f);
      float v3 = fmaxf(acc[mi][ni][3] + by, 0.f);
      __nv_bfloat16 h0, l0, h1, l1;
      bsplit(v0, h0, l0); bsplit(v1, h1, l1);
      *(uint32_t*)(sAhi + toff(row, kp)) = pack2(h0, h1);
      *(uint32_t*)(sAlo + toff(row, kp)) = pack2(l0, l1);
      bsplit(v2, h0, l0); bsplit(v3, h1, l1);
      *(uint32_t*)(sAhi + toff(row + 8, kp)) = pack2(h0, h1);
      *(uint32_t*)(sAlo + toff(row + 8, kp)) = pack2(l0, l1);
    }
  }
  __syncthreads();

  uint4* dsthi = (uint4*)(g_Ahi + (size_t)blk * TILE_W);
  uint4* dstlo = (uint4*)(g_Alo + (size_t)blk * TILE_W);
  for (int i = tid; i < 2048; i += 512) {
    int r = i >> 4, grp = i & 15;
    dsthi[i] = *(const uint4*)(sAhi + r * 272 + grp * 16);
    dstlo[i] = *(const uint4*)(sAlo + r * 272 + grp * 16);
  }
}

// ---------------- K2: fused HMMA GEMM2 (bf16x3) + tensor product + scatter --------
static constexpr int SM_AHI  = 0;
static constexpr int SM_ALO  = T68B;                    // 34816
static constexpr int SM_BHI  = 2 * T68B;                // 69632  (also sC staging)
static constexpr int SM_BLO  = 3 * T68B;                // 104448
static constexpr int SM_TPF  = 4 * T68B;                // 139264
static constexpr int FS_S    = SM_TPF / 4;              // 128*48
static constexpr int FS_DOT  = FS_S + 128 * 48;
static constexpr int FS_VIN  = FS_DOT + 128 * 10;
static constexpr int FS_SH   = FS_VIN + 128 * 30;
static constexpr int SM_BIAS = (FS_SH + 128 * 4) * 4;   // 186368
static constexpr int K2_SMEM = SM_BIAS + 512;           // 186880

__global__ __launch_bounds__(512) void k_fused(const int* __restrict__ eidx,
                                               const float* __restrict__ node_attr,
                                               const float* __restrict__ edge_sh,
                                               const float* __restrict__ b2) {
  extern __shared__ char smem[];
  float* smf   = (float*)smem;
  float* sC    = (float*)(smem + SM_BHI);   // C staging, pitch 132 (overlays B)
  float* sS    = smf + FS_S;
  float* sDot  = smf + FS_DOT;
  float* sVin  = smf + FS_VIN;
  float* sSh   = smf + FS_SH;
  float* sBias = (float*)(smem + SM_BIAS);
  uint32_t sb = smem_u32(smem);

  int tid = threadIdx.x;
  int wid = tid >> 5, lane = tid & 31;
  int blk = blockIdx.x;
  int e0 = blk * TB;

  // ---- A tiles: cp.async copy of pre-split h tiles ----
  {
    const char* srchi = (const char*)(g_Ahi + (size_t)blk * TILE_W);
    const char* srclo = (const char*)(g_Alo + (size_t)blk * TILE_W);
    for (int i = tid; i < 2048; i += 512) {
      int r = i >> 4, grp = i & 15;
      uint32_t d = (uint32_t)(r * 272 + grp * 16);
      cp16(sb + SM_AHI + d, srchi + i * 16);
      cp16(sb + SM_ALO + d, srclo + i * 16);
    }
  }

  int e_ = tid >> 2, q = tid & 3;   // 4 owner threads per edge

  // register accumulators (per owner thread)
  float rAc0[12];
#pragma unroll
  for (int i = 0; i < 12; ++i) rAc0[i] = 0.f;
  float rYa[3] = {0.f, 0.f, 0.f};
  float rYb[3][3];
#pragma unroll
  for (int i = 0; i < 3; ++i)
#pragma unroll
    for (int j = 0; j < 3; ++j) rYb[i][j] = 0.f;

  // left vectors
  {
    int eg = e0 + e_;
    if (eg < NEDGE) {
      int dst = eidx[NEDGE + eg];
      const float* x = node_attr + (size_t)dst * 78;
      for (int u = q * 12; u < q * 12 + 12; ++u) sS[e_ * 48 + u] = x[u];
      for (int m = q; m < 30; m += 4) sVin[e_ * 30 + m] = x[48 + m];
      if (q == 0)
        for (int i = 0; i < 4; ++i) sSh[e_ * 4 + i] = edge_sh[(size_t)eg * 4 + i];
    }
  }
  __syncthreads();
  {
    float s1 = sSh[e_ * 4 + 1], s2 = sSh[e_ * 4 + 2], s3 = sSh[e_ * 4 + 3];
    for (int u = q; u < 10; u += 4)
      sDot[e_ * 10 + u] = (sVin[e_ * 30 + u * 3] * s1 + sVin[e_ * 30 + u * 3 + 1] * s2 +
                           sVin[e_ * 30 + u * 3 + 2] * s3) * INV_SQRT3;
  }

  int m0 = (wid >> 2) * 32, n0 = (wid & 3) * 32;
  int g = lane >> 2, t = lane & 3;
  int lane15 = lane & 15;
  int khalf4 = (lane >> 4) << 2;

  for (int ci = 0; ci < NCHUNK; ++ci) {
    int type, jstart, cnt, rel;
    chunk_params(ci, type, jstart, cnt, rel);

    __syncthreads();   // prior epilogue done with sC before overwriting B region

    // ---- B tiles: cp.async copy of pre-split W2 chunk ----
    {
      const char* srchi = (const char*)(g_W2hi + (size_t)ci * TILE_W);
      const char* srclo = (const char*)(g_W2lo + (size_t)ci * TILE_W);
      for (int i = tid; i < 2048; i += 512) {
        int r = i >> 4, grp = i & 15;
        uint32_t d = (uint32_t)(r * 272 + grp * 16);
        cp16(sb + SM_BHI + d, srchi + i * 16);
        cp16(sb + SM_BLO + d, srclo + i * 16);
      }
    }
    if (tid < 128) sBias[tid] = (tid < cnt) ? b2[jstart + tid] : 0.f;
    cp_commit_wait_all();
    __syncthreads();   // B tiles (+A on ci==0) + bias ready

    // ---- 3-pass HMMA via ldmatrix: acc = Ah*Bh + Ah*Bl + Al*Bh ----
    float acc[2][4][4];
#pragma unroll
    for (int mi = 0; mi < 2; ++mi)
#pragma unroll
      for (int ni = 0; ni < 4; ++ni)
#pragma unroll
        for (int r = 0; r < 4; ++r) acc[mi][ni][r] = 0.f;

#pragma unroll
    for (int pass = 0; pass < 3; ++pass) {
      uint32_t pa = sb + ((pass == 2) ? SM_ALO : SM_AHI);
      uint32_t pb = sb + ((pass == 1) ? SM_BLO : SM_BHI);
      uint32_t aAd0 = pa + toff(m0 + lane15, khalf4);
      uint32_t aAd1 = aAd0 + 16 * 272;
      uint32_t bAd0 = pb + toff(n0 + lane15, khalf4);
      uint32_t bAd1 = bAd0 + 16 * 272;
#pragma unroll
      for (int ks = 0; ks < 8; ++ks) {
        uint32_t ko = (uint32_t)ks * 32;
        uint32_t a0[4], a1[4], b00, b01, b02, b03, b10, b11, b12, b13;
        ldsm4(a0[0], a0[1], a0[2], a0[3], aAd0 + ko);
        ldsm4(a1[0], a1[1], a1[2], a1[3], aAd1 + ko);
        ldsm4(b00, b01, b02, b03, bAd0 + ko);
        ldsm4(b10, b11, b12, b13, bAd1 + ko);
        mma16816(acc[0][0], a0, b00, b02);
        mma16816(acc[0][1], a0, b01, b03);
        mma16816(acc[0][2], a0, b10, b12);
        mma16816(acc[0][3], a0, b11, b13);
        mma16816(acc[1][0], a1, b00, b02);
        mma16816(acc[1][1], a1, b01, b03);
        mma16816(acc[1][2], a1, b10, b12);
        mma16816(acc[1][3], a1, b11, b13);
      }
    }
    __syncthreads();   // all MMA reads of sB done before sC overwrite

    // ---- C fragments + bias -> sC staging (pitch 132) ----
#pragma unroll
    for (int mi = 0; mi < 2; ++mi) {
      int row = m0 + mi * 16 + g;
#pragma unroll
      for (int ni = 0; ni < 4; ++ni) {
        int col = n0 + ni * 8 + 2 * t;
        float bx = sBias[col], by = sBias[col + 1];
        *(float2*)&sC[row * 132 + col] =
            make_float2(acc[mi][ni][0] + bx, acc[mi][ni][1] + by);
        *(float2*)&sC[(row + 8) * 132 + col] =
            make_float2(acc[mi][ni][2] + bx, acc[mi][ni][3] + by);
      }
    }
    __syncthreads();   // sC complete

    // ---- ownership-partitioned TP epilogue (4 threads per edge, reg accum) ----
    if (type == 1 || type == 4) {
      const float* mult = (type == 1) ? (sS + e_ * 48) : (sDot + e_ * 10);
      int umax = (type == 1) ? 47 : 9;
      const float* Cs = sC + e_ * 132 - rel;
#pragma unroll 4
      for (int vv = 0; vv < 12; ++vv) {
        int v = q * 12 + vv;
        int d = rel - v;
        int u0 = d > 0 ? (d + 47) / 48 : 0;
        int u1 = (rel + cnt - 1 - v) / 48; if (u1 > umax) u1 = umax;
        float p = 0.f;
        for (int u = u0; u <= u1; ++u) p = fmaf(Cs[u * 48 + v], mult[u], p);
        rAc0[vv] += p;
      }
    } else if (type == 2) {
      const float* Cs = sC + e_ * 132 - rel;
#pragma unroll
      for (int i = 0; i < 3; ++i) {
        int v = q + 4 * i;
        if (v < 10) {
          int d = rel - v;
          int u0 = d > 0 ? (d + 9) / 10 : 0;
          int u1 = (rel + cnt - 1 - v) / 10; if (u1 > 47) u1 = 47;
          float p = 0.f;
          for (int u = u0; u <= u1; ++u) p = fmaf(Cs[u * 10 + v], sS[e_ * 48 + u], p);
          rYa[i] += p;
        }
      }
    } else {  // w3
      const float* Cs = sC + e_ * 132;
#pragma unroll
      for (int i = 0; i < 3; ++i) {
        int v = q + 4 * i;
        if (v < 10) {
          float y0 = 0.f, y1 = 0.f, y2 = 0.f;
#pragma unroll
          for (int u = 0; u < 10; ++u) {
            float wv = Cs[u * 10 + v];
            y0 = fmaf(wv, sVin[e_ * 30 + u * 3 + 0], y0);
            y1 = fmaf(wv, sVin[e_ * 30 + u * 3 + 1], y1);
            y2 = fmaf(wv, sVin[e_ * 30 + u * 3 + 2], y2);
          }
          rYb[i][0] += y0; rYb[i][1] += y1; rYb[i][2] += y2;
        }
      }
    }

    if (ci == 3) {  // w2 phase done -> scale s by sh0 for the w1 phase
      __syncthreads();
      float s0 = sSh[e_ * 4 + 0];
      for (int vv = 0; vv < 12; ++vv) sS[e_ * 48 + q * 12 + vv] *= s0;
    }
  }
  __syncthreads();

  // ---- final per-edge output + scatter to node sums ----
  {
    int eg = e0 + e_;
    if (eg < NEDGE) {
      int src = eidx[eg];
      float s0 = sSh[e_ * 4], s1 = sSh[e_ * 4 + 1], s2 = sSh[e_ * 4 + 2], s3 = sSh[e_ * 4 + 3];
      float* dp = g_sum + (size_t)src * 78;
#pragma unroll
      for (int vv = 0; vv < 12; ++vv) {
        int v = q * 12 + vv;
        atomicAdd(&dp[v], rAc0[vv] * NORM01);
      }
#pragma unroll
      for (int i = 0; i < 3; ++i) {
        int v = q + 4 * i;
        if (v < 10) {
          atomicAdd(&dp[48 + v * 3 + 0], (rYa[i] * s1 + rYb[i][0] * s0) * NORM01);
          atomicAdd(&dp[48 + v * 3 + 1], (rYa[i] * s2 + rYb[i][1] * s0) * NORM01);
          atomicAdd(&dp[48 + v * 3 + 2], (rYa[i] * s3 + rYb[i][2] * s0) * NORM01);
        }
      }
      if (q == 0) atomicAdd(&g_cnt[src], 1.f);
    }
  }
}

// ---------------- K3: node finalize (mean + residual) + BN statistics ----------------
__global__ __launch_bounds__(256) void k_node(const float* __restrict__ node_attr,
                                              float* __restrict__ dout) {
  __shared__ float sP[106];
  int tid = threadIdx.x;
  if (tid < 106) sP[tid] = 0.f;
  __syncthreads();

  int n = blockIdx.x * blockDim.x + tid;
  bool valid = n < NNODE;
  float inv = 1.f;
  if (valid) inv = 1.f / fmaxf(g_cnt[n], 1.f);
  const float* srow  = g_sum + (valid ? (size_t)n * 78 : 0);
  const float* narow = node_attr + (valid ? (size_t)n * 78 : 0);

  for (int v = 0; v < 48; ++v) {
    float val = 0.f;
    if (valid) { val = srow[v] * inv + narow[v]; dout[(size_t)n * 78 + v] = val; }
    float s = val, qq = val * val;
#pragma unroll
    for (int o = 16; o; o >>= 1) {
      s += __shfl_xor_sync(0xffffffffu, s, o);
      qq += __shfl_xor_sync(0xffffffffu, qq, o);
    }
    if ((tid & 31) == 0) { atomicAdd(&sP[v], s); atomicAdd(&sP[48 + v], qq); }
  }
  for (int u = 0; u < 10; ++u) {
    float qq = 0.f;
    for (int i = 0; i < 3; ++i) {
      float val = 0.f;
      int c = 48 + u * 3 + i;
      if (valid) { val = srow[c] * inv + narow[c]; dout[(size_t)n * 78 + c] = val; }
      qq += val * val;
    }
#pragma unroll
    for (int o = 16; o; o >>= 1) qq += __shfl_xor_sync(0xffffffffu, qq, o);
    if ((tid & 31) == 0) atomicAdd(&sP[96 + u], qq);
  }
  __syncthreads();
  if (tid < 106) atomicAdd(&g_stats[tid], sP[tid]);
}

// ---------------- K4: apply batch norm in place ----------------
__global__ void k_bn(const float* __restrict__ bnw, const float* __restrict__ bnb,
                     float* __restrict__ dout) {
  int idx = blockIdx.x * blockDim.x + threadIdx.x;
  if (idx >= NNODE * 78) return;
  int c = idx % 78;
  float x = dout[idx];
  if (c < 48) {
    float mean = g_stats[c] * (1.f / NNODE);
    float var  = g_stats[48 + c] * (1.f / NNODE) - mean * mean;
    dout[idx] = (x - mean) * rsqrtf(var + EPS_BN) * bnw[c] + bnb[c];
  } else {
    int u = (c - 48) / 3;
    float vn = g_stats[96 + u] * (1.f / (3.f * NNODE));
    dout[idx] = x * rsqrtf(vn + EPS_BN) * bnw[48 + u];
  }
}

// ---------------- launch ----------------
extern "C" void kernel_launch(void* const* d_in, const int* in_sizes, int n_in,
                              void* d_out, int out_size) {
  const float* node_attr  = (const float*)d_in[0];
  const int*   edge_index = (const int*)d_in[1];
  const float* edge_attr  = (const float*)d_in[2];
  const float* edge_sh    = (const float*)d_in[3];
  const float* fc_w1      = (const float*)d_in[4];
  const float* fc_b1      = (const float*)d_in[5];
  const float* fc_w2      = (const float*)d_in[6];
  const float* fc_b2      = (const float*)d_in[7];
  const float* bn_w       = (const float*)d_in[8];
  const float* bn_b       = (const float*)d_in[9];
  float* out = (float*)d_out;

  cudaFuncSetAttribute(k_gemm1, cudaFuncAttributeMaxDynamicSharedMemorySize, K1_SMEM);
  cudaFuncSetAttribute(k_fused, cudaFuncAttributeMaxDynamicSharedMemorySize, K2_SMEM);

  k_zero<<<256, 256>>>();
  k_prep<<<432, 512>>>(fc_w1, fc_w2);
  k_gemm1<<<NBLK, 512, K1_SMEM>>>(edge_attr, fc_b1);
  k_fused<<<NBLK, 512, K2_SMEM>>>(edge_index, node_attr, edge_sh, fc_b2);
  k_node<<<(NNODE + 255) / 256, 256>>>(node_attr, out);
  k_bn<<<(NNODE * 78 + 255) / 256, 256>>>(bn_w, bn_b, out);
}

// round 13
// speedup vs baseline: 1.3431x; 1.0167x over previous
#include <cuda_runtime.h>
#include <cuda_bf16.h>
#include <cstdint>

// ---------------- problem constants ----------------
static constexpr int NNODE = 10000;
static constexpr int NEDGE = 50000;
static constexpr int HID   = 128;
static constexpr int WTOT  = 3364;  // 2304 + 480 + 100 + 480
static constexpr int OFF2  = 2304;
static constexpr int OFF3  = 2784;
static constexpr int OFF4  = 2884;
static constexpr int TB    = 128;
static constexpr int NBLK  = (NEDGE + TB - 1) / TB;    // 391
static constexpr int NCHUNK = 27;
static constexpr int TILE68_W = 128 * 68;              // words per padded tile (8704)
static constexpr int TILE_BYTES = TILE68_W * 4;        // 34816

#define EPS_BN     1e-5f
#define INV_SQRT3  0.57735026918962576f
#define NORM01     0.13130643285972254f   /* 1/sqrt(58) */

// ---------------- mma.sync / ldmatrix helpers (compile for sm_103) ----------
__device__ __forceinline__ void mma16816(float* c, const uint32_t* a,
                                         uint32_t b0, uint32_t b1) {
  asm volatile(
      "mma.sync.aligned.m16n8k16.row.col.f32.bf16.bf16.f32 "
      "{%0,%1,%2,%3}, {%4,%5,%6,%7}, {%8,%9}, {%0,%1,%2,%3};"
      : "+f"(c[0]), "+f"(c[1]), "+f"(c[2]), "+f"(c[3])
      : "r"(a[0]), "r"(a[1]), "r"(a[2]), "r"(a[3]), "r"(b0), "r"(b1));
}
__device__ __forceinline__ void ldsm4(uint32_t& r0, uint32_t& r1, uint32_t& r2,
                                      uint32_t& r3, uint32_t addr) {
  asm volatile("ldmatrix.sync.aligned.m8n8.x4.shared.b16 {%0,%1,%2,%3}, [%4];"
               : "=r"(r0), "=r"(r1), "=r"(r2), "=r"(r3) : "r"(addr));
}

// smem tile: row-major, 64 k-words (bf16x2) per row, pitch 68 words (272 B).
// NO swizzle: pitch 68 => 4-bank shift per row => conflict-free ldmatrix + builds.
__device__ __forceinline__ uint32_t toff(int row, int kp) {
  return (uint32_t)(row * 68 + kp) * 4u;
}

// bf16 hi/lo split
__device__ __forceinline__ void bsplit(float x, __nv_bfloat16& hi, __nv_bfloat16& lo) {
  hi = __float2bfloat16(x);
  lo = __float2bfloat16(x - __bfloat162float(hi));
}
__device__ __forceinline__ uint32_t pack2(__nv_bfloat16 a, __nv_bfloat16 b) {
  __nv_bfloat162 v; v.x = a; v.y = b;
  return *(uint32_t*)&v;
}

// ---------------- async bulk copy + mbarrier helpers ----------------
__device__ __forceinline__ uint32_t smem_u32(const void* p) {
  uint32_t a;
  asm("{ .reg .u64 t; cvta.to.shared.u64 t, %1; cvt.u32.u64 %0, t; }" : "=r"(a) : "l"(p));
  return a;
}
__device__ __forceinline__ void mbar_init(uint32_t mbar, uint32_t cnt) {
  asm volatile("mbarrier.init.shared.b64 [%0], %1;" :: "r"(mbar), "r"(cnt) : "memory");
}
__device__ __forceinline__ void mbar_expect_tx(uint32_t mbar, uint32_t bytes) {
  asm volatile("mbarrier.arrive.expect_tx.shared.b64 _, [%0], %1;"
               :: "r"(mbar), "r"(bytes) : "memory");
}
__device__ __forceinline__ void mbar_wait(uint32_t mbar, uint32_t parity) {
  asm volatile(
      "{\n\t.reg .pred P;\n\t"
      "WL_%=:\n\t"
      "mbarrier.try_wait.parity.acquire.cta.shared::cta.b64 P, [%0], %1, 0x989680;\n\t"
      "@P bra.uni WD_%=;\n\t"
      "bra.uni WL_%=;\n\t"
      "WD_%=:\n\t}"
      :: "r"(mbar), "r"(parity) : "memory");
}
__device__ __forceinline__ void bulk_cp(uint32_t dst, const void* src,
                                        uint32_t bytes, uint32_t mbar) {
  asm volatile(
      "cp.async.bulk.shared::cluster.global.mbarrier::complete_tx::bytes [%0], [%1], %2, [%3];"
      :: "r"(dst), "l"(src), "r"(bytes), "r"(mbar) : "memory");
}
__device__ __forceinline__ void fence_proxy_async_cta() {
  asm volatile("fence.proxy.async.shared::cta;" ::: "memory");
}

// chunk schedule (shared by k_prep / k_fused)
__device__ __forceinline__ void chunk_params(int ci, int& type, int& jstart,
                                             int& cnt, int& rel) {
  if (ci < 4)       { type = 2; rel = ci * 120;        jstart = OFF2 + rel; cnt = 120; }
  else if (ci < 22) { type = 1; rel = (ci - 4) * 128;  jstart = rel;        cnt = 128; }
  else if (ci < 26) { type = 4; rel = (ci - 22) * 120; jstart = OFF4 + rel; cnt = 120; }
  else              { type = 3; rel = 0;               jstart = OFF3;       cnt = 100; }
}

// ---------------- scratch (global byte-images of smem tiles, pitch 68) ------------
__device__ __align__(256) uint32_t g_Ahi[(size_t)NBLK * TILE68_W];
__device__ __align__(256) uint32_t g_Alo[(size_t)NBLK * TILE68_W];
__device__ __align__(256) uint32_t g_W2hi[(size_t)NCHUNK * TILE68_W];
__device__ __align__(256) uint32_t g_W2lo[(size_t)NCHUNK * TILE68_W];
__device__ __align__(256) uint32_t g_W1hi[TILE68_W];
__device__ __align__(256) uint32_t g_W1lo[TILE68_W];
__device__ float g_sum[(size_t)NNODE * 78];
__device__ float g_cnt[NNODE];
__device__ float g_stats[106];

// ---------------- K0: zero scratch ----------------
__global__ void k_zero() {
  int idx = blockIdx.x * blockDim.x + threadIdx.x;
  int stride = gridDim.x * blockDim.x;
  for (int i = idx; i < NNODE * 78; i += stride) g_sum[i] = 0.f;
  for (int i = idx; i < NNODE; i += stride) g_cnt[i] = 0.f;
  if (idx < 106) g_stats[idx] = 0.f;
}

// ---------------- Kp: pre-split W1 / W2 into padded bf16 hi/lo tile images ----------
__global__ void k_prep(const float* __restrict__ W1, const float* __restrict__ W2) {
  int idx = blockIdx.x * blockDim.x + threadIdx.x;
  int stride = gridDim.x * blockDim.x;
  int total = (NCHUNK + 1) * TILE68_W;
  for (int i = idx; i < total; i += stride) {
    int tile = i / TILE68_W;
    int r = i - tile * TILE68_W;
    int row = r / 68, kp = r % 68;
    if (tile < NCHUNK) {
      int type, jstart, cnt, rel;
      chunk_params(tile, type, jstart, cnt, rel);
      float x0 = 0.f, x1 = 0.f;
      if (kp < 64 && row < cnt) {
        x0 = W2[(size_t)(2 * kp) * WTOT + jstart + row];
        x1 = W2[(size_t)(2 * kp + 1) * WTOT + jstart + row];
      }
      __nv_bfloat16 h0, l0, h1, l1;
      bsplit(x0, h0, l0); bsplit(x1, h1, l1);
      g_W2hi[i] = pack2(h0, h1);
      g_W2lo[i] = pack2(l0, l1);
    } else {
      float x0 = 0.f, x1 = 0.f;
      if (kp < 64) {
        x0 = W1[(size_t)(2 * kp) * 128 + row];
        x1 = W1[(size_t)(2 * kp + 1) * 128 + row];
      }
      __nv_bfloat16 h0, l0, h1, l1;
      bsplit(x0, h0, l0); bsplit(x1, h1, l1);
      g_W1hi[r] = pack2(h0, h1);
      g_W1lo[r] = pack2(l0, l1);
    }
  }
}

// ---------------- K1: HMMA h = relu(edge_attr @ W1 + b1) -> bf16 hi/lo A tiles ------
static constexpr int T68B   = TILE_BYTES;               // 34816 per smem tile
static constexpr int K1_MBAR = 4 * T68B;                // 139264
static constexpr int K1_SMEM = K1_MBAR + 16;

__global__ __launch_bounds__(512) void k_gemm1(const float* __restrict__ A,
                                               const float* __restrict__ b1) {
  extern __shared__ char smem[];
  char* sAhi = smem;
  char* sAlo = smem + T68B;
  uint32_t sb = smem_u32(smem);
  uint32_t mbar = sb + K1_MBAR;

  int tid = threadIdx.x;
  int wid = tid >> 5, lane = tid & 31;
  int blk = blockIdx.x;
  int e0 = blk * TB;

  // B tiles: bulk copy of W1 hi/lo images
  if (tid == 0) {
    mbar_init(mbar, 1);
    fence_proxy_async_cta();
    mbar_expect_tx(mbar, 2 * TILE_BYTES);
    bulk_cp(sb + 2 * T68B, g_W1hi, TILE_BYTES, mbar);
    bulk_cp(sb + 3 * T68B, g_W1lo, TILE_BYTES, mbar);
  }

  // A tiles: load edge_attr fp32 (coalesced), split, store pitch-68
  for (int i = tid; i < 128 * 64; i += 512) {
    int e = i >> 6, kp = i & 63;
    float2 x = make_float2(0.f, 0.f);
    if (e0 + e < NEDGE) x = *(const float2*)&A[(size_t)(e0 + e) * 128 + 2 * kp];
    __nv_bfloat16 h0, l0, h1, l1;
    bsplit(x.x, h0, l0); bsplit(x.y, h1, l1);
    uint32_t off = toff(e, kp);
    *(uint32_t*)(sAhi + off) = pack2(h0, h1);
    *(uint32_t*)(sAlo + off) = pack2(l0, l1);
  }
  mbar_wait(mbar, 0);
  __syncthreads();

  int m0 = (wid >> 2) * 32, n0 = (wid & 3) * 32;
  int g = lane >> 2, t = lane & 3;
  int lane15 = lane & 15;
  int khalf4 = (lane >> 4) << 2;   // 0 or 4 (k-word offset for ldmatrix halves)

  float acc[2][4][4];
#pragma unroll
  for (int mi = 0; mi < 2; ++mi)
#pragma unroll
    for (int ni = 0; ni < 4; ++ni)
#pragma unroll
      for (int r = 0; r < 4; ++r) acc[mi][ni][r] = 0.f;

#pragma unroll
  for (int pass = 0; pass < 3; ++pass) {
    uint32_t pa = sb + ((pass == 2) ? T68B : 0);
    uint32_t pb = sb + ((pass == 1) ? 3 * T68B : 2 * T68B);
    uint32_t aAd0 = pa + toff(m0 + lane15, khalf4);
    uint32_t aAd1 = aAd0 + 16 * 272;
    uint32_t bAd0 = pb + toff(n0 + lane15, khalf4);
    uint32_t bAd1 = bAd0 + 16 * 272;
#pragma unroll
    for (int ks = 0; ks < 8; ++ks) {
      uint32_t ko = (uint32_t)ks * 32;
      uint32_t a0[4], a1[4], b00, b01, b02, b03, b10, b11, b12, b13;
      ldsm4(a0[0], a0[1], a0[2], a0[3], aAd0 + ko);
      ldsm4(a1[0], a1[1], a1[2], a1[3], aAd1 + ko);
      ldsm4(b00, b01, b02, b03, bAd0 + ko);
      ldsm4(b10, b11, b12, b13, bAd1 + ko);
      mma16816(acc[0][0], a0, b00, b02);
      mma16816(acc[0][1], a0, b01, b03);
      mma16816(acc[0][2], a0, b10, b12);
      mma16816(acc[0][3], a0, b11, b13);
      mma16816(acc[1][0], a1, b00, b02);
      mma16816(acc[1][1], a1, b01, b03);
      mma16816(acc[1][2], a1, b10, b12);
      mma16816(acc[1][3], a1, b11, b13);
    }
  }
  __syncthreads();   // done reading A tiles; reuse sAhi/sAlo as export staging

  // epilogue: +bias, relu, split -> smem (pitch 68), then coalesced export
#pragma unroll
  for (int ni = 0; ni < 4; ++ni) {
    int c0 = n0 + ni * 8 + 2 * t;
    int kp = c0 >> 1;
    float bx = b1[c0], by = b1[c0 + 1];
#pragma unroll
    for (int mi = 0; mi < 2; ++mi) {
      int row = m0 + mi * 16 + g;
      float v0 = fmaxf(acc[mi][ni][0] + bx, 0.f);
      float v1 = fmaxf(acc[mi][ni][1] + by, 0.f);
      float v2 = fmaxf(acc[mi][ni][2] + bx, 0.f);
      float v3 = fmaxf(acc[mi][ni][3] + by, 0.f);
      __nv_bfloat16 h0, l0, h1, l1;
      bsplit(v0, h0, l0); bsplit(v1, h1, l1);
      *(uint32_t*)(sAhi + toff(row, kp)) = pack2(h0, h1);
      *(uint32_t*)(sAlo + toff(row, kp)) = pack2(l0, l1);
      bsplit(v2, h0, l0); bsplit(v3, h1, l1);
      *(uint32_t*)(sAhi + toff(row + 8, kp)) = pack2(h0, h1);
      *(uint32_t*)(sAlo + toff(row + 8, kp)) = pack2(l0, l1);
    }
  }
  __syncthreads();

  // export full padded tile images (pad bytes carry garbage; never read as data)
  uint4* dsthi = (uint4*)(g_Ahi + (size_t)blk * TILE68_W);
  uint4* dstlo = (uint4*)(g_Alo + (size_t)blk * TILE68_W);
  for (int i = tid; i < TILE_BYTES / 16; i += 512) {
    dsthi[i] = *(const uint4*)(sAhi + i * 16);
    dstlo[i] = *(const uint4*)(sAlo + i * 16);
  }
}

// ---------------- K2: fused HMMA GEMM2 (bf16x3) + tensor product + scatter --------
static constexpr int SM_AHI  = 0;
static constexpr int SM_ALO  = T68B;                    // 34816
static constexpr int SM_BHI  = 2 * T68B;                // 69632  (also sC staging)
static constexpr int SM_BLO  = 3 * T68B;                // 104448
static constexpr int SM_TPF  = 4 * T68B;                // 139264
static constexpr int FS_S    = SM_TPF / 4;              // 128*48
static constexpr int FS_DOT  = FS_S + 128 * 48;
static constexpr int FS_VIN  = FS_DOT + 128 * 10;
static constexpr int FS_SH   = FS_VIN + 128 * 30;
static constexpr int SM_BIAS = (FS_SH + 128 * 4) * 4;   // 186368
static constexpr int SM_MBAR = SM_BIAS + 512;           // 186880
static constexpr int K2_SMEM = SM_MBAR + 16;

__global__ __launch_bounds__(512) void k_fused(const int* __restrict__ eidx,
                                               const float* __restrict__ node_attr,
                                               const float* __restrict__ edge_sh,
                                               const float* __restrict__ b2) {
  extern __shared__ char smem[];
  float* smf   = (float*)smem;
  float* sC    = (float*)(smem + SM_BHI);   // C staging, pitch 132 (overlays B)
  float* sS    = smf + FS_S;
  float* sDot  = smf + FS_DOT;
  float* sVin  = smf + FS_VIN;
  float* sSh   = smf + FS_SH;
  float* sBias = (float*)(smem + SM_BIAS);
  uint32_t sb = smem_u32(smem);
  uint32_t mbar = sb + SM_MBAR;

  int tid = threadIdx.x;
  int wid = tid >> 5, lane = tid & 31;
  int blk = blockIdx.x;
  int e0 = blk * TB;

  // phase 0: A tiles + B chunk 0, all via bulk copies
  if (tid == 0) {
    mbar_init(mbar, 1);
    fence_proxy_async_cta();
    mbar_expect_tx(mbar, 4 * TILE_BYTES);
    bulk_cp(sb + SM_AHI, g_Ahi + (size_t)blk * TILE68_W, TILE_BYTES, mbar);
    bulk_cp(sb + SM_ALO, g_Alo + (size_t)blk * TILE68_W, TILE_BYTES, mbar);
    bulk_cp(sb + SM_BHI, g_W2hi, TILE_BYTES, mbar);
    bulk_cp(sb + SM_BLO, g_W2lo, TILE_BYTES, mbar);
  }

  int e_ = tid >> 2, q = tid & 3;   // 4 owner threads per edge

  // register accumulators (per owner thread)
  float rAc0[12];
#pragma unroll
  for (int i = 0; i < 12; ++i) rAc0[i] = 0.f;
  float rYa[3] = {0.f, 0.f, 0.f};
  float rYb[3][3];
#pragma unroll
  for (int i = 0; i < 3; ++i)
#pragma unroll
    for (int j = 0; j < 3; ++j) rYb[i][j] = 0.f;

  // left vectors (generic loads, overlap the bulk copies)
  {
    int eg = e0 + e_;
    if (eg < NEDGE) {
      int dst = eidx[NEDGE + eg];
      const float* x = node_attr + (size_t)dst * 78;
      for (int u = q * 12; u < q * 12 + 12; ++u) sS[e_ * 48 + u] = x[u];
      for (int m = q; m < 30; m += 4) sVin[e_ * 30 + m] = x[48 + m];
      if (q == 0)
        for (int i = 0; i < 4; ++i) sSh[e_ * 4 + i] = edge_sh[(size_t)eg * 4 + i];
    }
  }
  __syncthreads();
  {
    float s1 = sSh[e_ * 4 + 1], s2 = sSh[e_ * 4 + 2], s3 = sSh[e_ * 4 + 3];
    for (int u = q; u < 10; u += 4)
      sDot[e_ * 10 + u] = (sVin[e_ * 30 + u * 3] * s1 + sVin[e_ * 30 + u * 3 + 1] * s2 +
                           sVin[e_ * 30 + u * 3 + 2] * s3) * INV_SQRT3;
  }

  int m0 = (wid >> 2) * 32, n0 = (wid & 3) * 32;
  int g = lane >> 2, t = lane & 3;
  int lane15 = lane & 15;
  int khalf4 = (lane >> 4) << 2;

  for (int ci = 0; ci < NCHUNK; ++ci) {
    int type, jstart, cnt, rel;
    chunk_params(ci, type, jstart, cnt, rel);

    if (ci > 0) {
      __syncthreads();   // prior epilogue done with sC before overwriting B region
      if (tid == 0) {
        fence_proxy_async_cta();
        mbar_expect_tx(mbar, 2 * TILE_BYTES);
        bulk_cp(sb + SM_BHI, g_W2hi + (size_t)ci * TILE68_W, TILE_BYTES, mbar);
        bulk_cp(sb + SM_BLO, g_W2lo + (size_t)ci * TILE68_W, TILE_BYTES, mbar);
      }
    }
    if (tid < 128) sBias[tid] = (tid < cnt) ? b2[jstart + tid] : 0.f;
    mbar_wait(mbar, (uint32_t)(ci & 1));
    __syncthreads();   // tiles + bias visible to all

    // ---- 3-pass HMMA via ldmatrix: acc = Ah*Bh + Ah*Bl + Al*Bh ----
    float acc[2][4][4];
#pragma unroll
    for (int mi = 0; mi < 2; ++mi)
#pragma unroll
      for (int ni = 0; ni < 4; ++ni)
#pragma unroll
        for (int r = 0; r < 4; ++r) acc[mi][ni][r] = 0.f;

#pragma unroll
    for (int pass = 0; pass < 3; ++pass) {
      uint32_t pa = sb + ((pass == 2) ? SM_ALO : SM_AHI);
      uint32_t pb = sb + ((pass == 1) ? SM_BLO : SM_BHI);
      uint32_t aAd0 = pa + toff(m0 + lane15, khalf4);
      uint32_t aAd1 = aAd0 + 16 * 272;
      uint32_t bAd0 = pb + toff(n0 + lane15, khalf4);
      uint32_t bAd1 = bAd0 + 16 * 272;
#pragma unroll
      for (int ks = 0; ks < 8; ++ks) {
        uint32_t ko = (uint32_t)ks * 32;
        uint32_t a0[4], a1[4], b00, b01, b02, b03, b10, b11, b12, b13;
        ldsm4(a0[0], a0[1], a0[2], a0[3], aAd0 + ko);
        ldsm4(a1[0], a1[1], a1[2], a1[3], aAd1 + ko);
        ldsm4(b00, b01, b02, b03, bAd0 + ko);
        ldsm4(b10, b11, b12, b13, bAd1 + ko);
        mma16816(acc[0][0], a0, b00, b02);
        mma16816(acc[0][1], a0, b01, b03);
        mma16816(acc[0][2], a0, b10, b12);
        mma16816(acc[0][3], a0, b11, b13);
        mma16816(acc[1][0], a1, b00, b02);
        mma16816(acc[1][1], a1, b01, b03);
        mma16816(acc[1][2], a1, b10, b12);
        mma16816(acc[1][3], a1, b11, b13);
      }
    }
    __syncthreads();   // all MMA reads of sB done before sC overwrite

    // ---- C fragments + bias -> sC staging (pitch 132) ----
#pragma unroll
    for (int mi = 0; mi < 2; ++mi) {
      int row = m0 + mi * 16 + g;
#pragma unroll
      for (int ni = 0; ni < 4; ++ni) {
        int col = n0 + ni * 8 + 2 * t;
        float bx = sBias[col], by = sBias[col + 1];
        *(float2*)&sC[row * 132 + col] =
            make_float2(acc[mi][ni][0] + bx, acc[mi][ni][1] + by);
        *(float2*)&sC[(row + 8) * 132 + col] =
            make_float2(acc[mi][ni][2] + bx, acc[mi][ni][3] + by);
      }
    }
    __syncthreads();   // sC complete

    // ---- ownership-partitioned TP epilogue (4 threads per edge, reg accum) ----
    if (type == 1 || type == 4) {
      const float* mult = (type == 1) ? (sS + e_ * 48) : (sDot + e_ * 10);
      int umax = (type == 1) ? 47 : 9;
      const float* Cs = sC + e_ * 132 - rel;
#pragma unroll 4
      for (int vv = 0; vv < 12; ++vv) {
        int v = q * 12 + vv;
        int d = rel - v;
        int u0 = d > 0 ? (d + 47) / 48 : 0;
        int u1 = (rel + cnt - 1 - v) / 48; if (u1 > umax) u1 = umax;
        float p = 0.f;
        for (int u = u0; u <= u1; ++u) p = fmaf(Cs[u * 48 + v], mult[u], p);
        rAc0[vv] += p;
      }
    } else if (type == 2) {
      const float* Cs = sC + e_ * 132 - rel;
#pragma unroll
      for (int i = 0; i < 3; ++i) {
        int v = q + 4 * i;
        if (v < 10) {
          int d = rel - v;
          int u0 = d > 0 ? (d + 9) / 10 : 0;
          int u1 = (rel + cnt - 1 - v) / 10; if (u1 > 47) u1 = 47;
          float p = 0.f;
          for (int u = u0; u <= u1; ++u) p = fmaf(Cs[u * 10 + v], sS[e_ * 48 + u], p);
          rYa[i] += p;
        }
      }
    } else {  // w3
      const float* Cs = sC + e_ * 132;
#pragma unroll
      for (int i = 0; i < 3; ++i) {
        int v = q + 4 * i;
        if (v < 10) {
          float y0 = 0.f, y1 = 0.f, y2 = 0.f;
#pragma unroll
          for (int u = 0; u < 10; ++u) {
            float wv = Cs[u * 10 + v];
            y0 = fmaf(wv, sVin[e_ * 30 + u * 3 + 0], y0);
            y1 = fmaf(wv, sVin[e_ * 30 + u * 3 + 1], y1);
            y2 = fmaf(wv, sVin[e_ * 30 + u * 3 + 2], y2);
          }
          rYb[i][0] += y0; rYb[i][1] += y1; rYb[i][2] += y2;
        }
      }
    }

    if (ci == 3) {  // w2 phase done -> scale s by sh0 for the w1 phase
      __syncthreads();
      float s0 = sSh[e_ * 4 + 0];
      for (int vv = 0; vv < 12; ++vv) sS[e_ * 48 + q * 12 + vv] *= s0;
    }
  }
  __syncthreads();

  // ---- final per-edge output + scatter to node sums ----
  {
    int eg = e0 + e_;
    if (eg < NEDGE) {
      int src = eidx[eg];
      float s0 = sSh[e_ * 4], s1 = sSh[e_ * 4 + 1], s2 = sSh[e_ * 4 + 2], s3 = sSh[e_ * 4 + 3];
      float* dp = g_sum + (size_t)src * 78;
#pragma unroll
      for (int vv = 0; vv < 12; ++vv) {
        int v = q * 12 + vv;
        atomicAdd(&dp[v], rAc0[vv] * NORM01);
      }
#pragma unroll
      for (int i = 0; i < 3; ++i) {
        int v = q + 4 * i;
        if (v < 10) {
          atomicAdd(&dp[48 + v * 3 + 0], (rYa[i] * s1 + rYb[i][0] * s0) * NORM01);
          atomicAdd(&dp[48 + v * 3 + 1], (rYa[i] * s2 + rYb[i][1] * s0) * NORM01);
          atomicAdd(&dp[48 + v * 3 + 2], (rYa[i] * s3 + rYb[i][2] * s0) * NORM01);
        }
      }
      if (q == 0) atomicAdd(&g_cnt[src], 1.f);
    }
  }
}

// ---------------- K3: node finalize (mean + residual) + BN statistics ----------------
__global__ __launch_bounds__(256) void k_node(const float* __restrict__ node_attr,
                                              float* __restrict__ dout) {
  __shared__ float sP[106];
  int tid = threadIdx.x;
  if (tid < 106) sP[tid] = 0.f;
  __syncthreads();

  int n = blockIdx.x * blockDim.x + tid;
  bool valid = n < NNODE;
  float inv = 1.f;
  if (valid) inv = 1.f / fmaxf(g_cnt[n], 1.f);
  const float* srow  = g_sum + (valid ? (size_t)n * 78 : 0);
  const float* narow = node_attr + (valid ? (size_t)n * 78 : 0);

  for (int v = 0; v < 48; ++v) {
    float val = 0.f;
    if (valid) { val = srow[v] * inv + narow[v]; dout[(size_t)n * 78 + v] = val; }
    float s = val, qq = val * val;
#pragma unroll
    for (int o = 16; o; o >>= 1) {
      s += __shfl_xor_sync(0xffffffffu, s, o);
      qq += __shfl_xor_sync(0xffffffffu, qq, o);
    }
    if ((tid & 31) == 0) { atomicAdd(&sP[v], s); atomicAdd(&sP[48 + v], qq); }
  }
  for (int u = 0; u < 10; ++u) {
    float qq = 0.f;
    for (int i = 0; i < 3; ++i) {
      float val = 0.f;
      int c = 48 + u * 3 + i;
      if (valid) { val = srow[c] * inv + narow[c]; dout[(size_t)n * 78 + c] = val; }
      qq += val * val;
    }
#pragma unroll
    for (int o = 16; o; o >>= 1) qq += __shfl_xor_sync(0xffffffffu, qq, o);
    if ((tid & 31) == 0) atomicAdd(&sP[96 + u], qq);
  }
  __syncthreads();
  if (tid < 106) atomicAdd(&g_stats[tid], sP[tid]);
}

// ---------------- K4: apply batch norm in place ----------------
__global__ void k_bn(const float* __restrict__ bnw, const float* __restrict__ bnb,
                     float* __restrict__ dout) {
  int idx = blockIdx.x * blockDim.x + threadIdx.x;
  if (idx >= NNODE * 78) return;
  int c = idx % 78;
  float x = dout[idx];
  if (c < 48) {
    float mean = g_stats[c] * (1.f / NNODE);
    float var  = g_stats[48 + c] * (1.f / NNODE) - mean * mean;
    dout[idx] = (x - mean) * rsqrtf(var + EPS_BN) * bnw[c] + bnb[c];
  } else {
    int u = (c - 48) / 3;
    float vn = g_stats[96 + u] * (1.f / (3.f * NNODE));
    dout[idx] = x * rsqrtf(vn + EPS_BN) * bnw[48 + u];
  }
}

// ---------------- launch ----------------
extern "C" void kernel_launch(void* const* d_in, const int* in_sizes, int n_in,
                              void* d_out, int out_size) {
  const float* node_attr  = (const float*)d_in[0];
  const int*   edge_index = (const int*)d_in[1];
  const float* edge_attr  = (const float*)d_in[2];
  const float* edge_sh    = (const float*)d_in[3];
  const float* fc_w1      = (const float*)d_in[4];
  const float* fc_b1      = (const float*)d_in[5];
  const float* fc_w2      = (const float*)d_in[6];
  const float* fc_b2      = (const float*)d_in[7];
  const float* bn_w       = (const float*)d_in[8];
  const float* bn_b       = (const float*)d_in[9];
  float* out = (float*)d_out;

  cudaFuncSetAttribute(k_gemm1, cudaFuncAttributeMaxDynamicSharedMemorySize, K1_SMEM);
  cudaFuncSetAttribute(k_fused, cudaFuncAttributeMaxDynamicSharedMemorySize, K2_SMEM);

  k_zero<<<256, 256>>>();
  k_prep<<<432, 512>>>(fc_w1, fc_w2);
  k_gemm1<<<NBLK, 512, K1_SMEM>>>(edge_attr, fc_b1);
  k_fused<<<NBLK, 512, K2_SMEM>>>(edge_index, node_attr, edge_sh, fc_b2);
  k_node<<<(NNODE + 255) / 256, 256>>>(node_attr, out);
  k_bn<<<(NNODE * 78 + 255) / 256, 256>>>(bn_w, bn_b, out);
}

// round 14
// speedup vs baseline: 1.4620x; 1.0885x over previous
#include <cuda_runtime.h>
#include <cuda_bf16.h>
#include <cstdint>

// ---------------- problem constants ----------------
static constexpr int NNODE = 10000;
static constexpr int NEDGE = 50000;
static constexpr int WTOT  = 3364;  // 2304 + 480 + 100 + 480
static constexpr int OFF2  = 2304;
static constexpr int OFF3  = 2784;
static constexpr int OFF4  = 2884;
static constexpr int TB    = 64;                       // edges per tile
static constexpr int NBLK  = (NEDGE + TB - 1) / TB;    // 782
static constexpr int NCHUNK = 54;                      // N=64 sub-chunks
static constexpr int T2W   = 64 * 68;                  // words per 64-row tile (4352)
static constexpr int T1W   = 128 * 68;                 // words per 128-row tile (8704)
static constexpr int T64B  = T2W * 4;                  // 17408 bytes
static constexpr int T128B = T1W * 4;                  // 34816 bytes

#define EPS_BN     1e-5f
#define INV_SQRT3  0.57735026918962576f
#define NORM01     0.13130643285972254f   /* 1/sqrt(58) */

// ---------------- mma.sync / ldmatrix helpers (compile for sm_103) ----------
__device__ __forceinline__ void mma16816(float* c, const uint32_t* a,
                                         uint32_t b0, uint32_t b1) {
  asm volatile(
      "mma.sync.aligned.m16n8k16.row.col.f32.bf16.bf16.f32 "
      "{%0,%1,%2,%3}, {%4,%5,%6,%7}, {%8,%9}, {%0,%1,%2,%3};"
      : "+f"(c[0]), "+f"(c[1]), "+f"(c[2]), "+f"(c[3])
      : "r"(a[0]), "r"(a[1]), "r"(a[2]), "r"(a[3]), "r"(b0), "r"(b1));
}
__device__ __forceinline__ void ldsm4(uint32_t& r0, uint32_t& r1, uint32_t& r2,
                                      uint32_t& r3, uint32_t addr) {
  asm volatile("ldmatrix.sync.aligned.m8n8.x4.shared.b16 {%0,%1,%2,%3}, [%4];"
               : "=r"(r0), "=r"(r1), "=r"(r2), "=r"(r3) : "r"(addr));
}

// smem tile: row-major, 64 k-words (bf16x2)/row, pitch 68 words (272 B).
// pitch 68 => 4-bank shift per row => conflict-free ldmatrix + builds.
__device__ __forceinline__ uint32_t toff(int row, int kp) {
  return (uint32_t)(row * 68 + kp) * 4u;
}

// bf16 hi/lo split
__device__ __forceinline__ void bsplit(float x, __nv_bfloat16& hi, __nv_bfloat16& lo) {
  hi = __float2bfloat16(x);
  lo = __float2bfloat16(x - __bfloat162float(hi));
}
__device__ __forceinline__ uint32_t pack2(__nv_bfloat16 a, __nv_bfloat16 b) {
  __nv_bfloat162 v; v.x = a; v.y = b;
  return *(uint32_t*)&v;
}

// ---------------- async bulk copy + mbarrier helpers ----------------
__device__ __forceinline__ uint32_t smem_u32(const void* p) {
  uint32_t a;
  asm("{ .reg .u64 t; cvta.to.shared.u64 t, %1; cvt.u32.u64 %0, t; }" : "=r"(a) : "l"(p));
  return a;
}
__device__ __forceinline__ void mbar_init(uint32_t mbar, uint32_t cnt) {
  asm volatile("mbarrier.init.shared.b64 [%0], %1;" :: "r"(mbar), "r"(cnt) : "memory");
}
__device__ __forceinline__ void mbar_expect_tx(uint32_t mbar, uint32_t bytes) {
  asm volatile("mbarrier.arrive.expect_tx.shared.b64 _, [%0], %1;"
               :: "r"(mbar), "r"(bytes) : "memory");
}
__device__ __forceinline__ void mbar_wait(uint32_t mbar, uint32_t parity) {
  asm volatile(
      "{\n\t.reg .pred P;\n\t"
      "WL_%=:\n\t"
      "mbarrier.try_wait.parity.acquire.cta.shared::cta.b64 P, [%0], %1, 0x989680;\n\t"
      "@P bra.uni WD_%=;\n\t"
      "bra.uni WL_%=;\n\t"
      "WD_%=:\n\t}"
      :: "r"(mbar), "r"(parity) : "memory");
}
__device__ __forceinline__ void bulk_cp(uint32_t dst, const void* src,
                                        uint32_t bytes, uint32_t mbar) {
  asm volatile(
      "cp.async.bulk.shared::cluster.global.mbarrier::complete_tx::bytes [%0], [%1], %2, [%3];"
      :: "r"(dst), "l"(src), "r"(bytes), "r"(mbar) : "memory");
}
__device__ __forceinline__ void fence_proxy_async_cta() {
  asm volatile("fence.proxy.async.shared::cta;" ::: "memory");
}

// chunk schedule: 8x w2 -> 36x w1 -> 8x w4 -> 2x w3, all N<=64
__device__ __forceinline__ void chunk_params(int ci, int& type, int& jstart,
                                             int& cnt, int& rel) {
  if (ci < 8)       { type = 2; rel = ci * 64;        cnt = (rel + 64 <= 480) ? 64 : 480 - rel; jstart = OFF2 + rel; }
  else if (ci < 44) { type = 1; rel = (ci - 8) * 64;  cnt = 64;                                  jstart = rel; }
  else if (ci < 52) { type = 4; rel = (ci - 44) * 64; cnt = (rel + 64 <= 480) ? 64 : 480 - rel;  jstart = OFF4 + rel; }
  else              { type = 3; rel = (ci - 52) * 64; cnt = (rel + 64 <= 100) ? 64 : 100 - rel;  jstart = OFF3 + rel; }
}

// ---------------- scratch (global byte-images of smem tiles, pitch 68) ------------
__device__ __align__(256) uint32_t g_Ahi[(size_t)NBLK * T2W];
__device__ __align__(256) uint32_t g_Alo[(size_t)NBLK * T2W];
__device__ __align__(256) uint32_t g_W2hi[(size_t)NCHUNK * T2W];
__device__ __align__(256) uint32_t g_W2lo[(size_t)NCHUNK * T2W];
__device__ __align__(256) uint32_t g_W1hi[T1W];
__device__ __align__(256) uint32_t g_W1lo[T1W];
__device__ float g_sum[(size_t)NNODE * 78];
__device__ float g_cnt[NNODE];
__device__ float g_stats[106];

// ---------------- K0: zero scratch ----------------
__global__ void k_zero() {
  int idx = blockIdx.x * blockDim.x + threadIdx.x;
  int stride = gridDim.x * blockDim.x;
  for (int i = idx; i < NNODE * 78; i += stride) g_sum[i] = 0.f;
  for (int i = idx; i < NNODE; i += stride) g_cnt[i] = 0.f;
  if (idx < 106) g_stats[idx] = 0.f;
}

// ---------------- Kp: pre-split W1 / W2 into padded bf16 hi/lo tile images ----------
__global__ void k_prep(const float* __restrict__ W1, const float* __restrict__ W2) {
  int idx = blockIdx.x * blockDim.x + threadIdx.x;
  int stride = gridDim.x * blockDim.x;
  int total = NCHUNK * T2W + T1W;
  for (int i = idx; i < total; i += stride) {
    if (i < NCHUNK * T2W) {
      int tile = i / T2W;
      int r = i - tile * T2W;
      int row = r / 68, kp = r % 68;
      int type, jstart, cnt, rel;
      chunk_params(tile, type, jstart, cnt, rel);
      float x0 = 0.f, x1 = 0.f;
      if (kp < 64 && row < cnt) {
        x0 = W2[(size_t)(2 * kp) * WTOT + jstart + row];
        x1 = W2[(size_t)(2 * kp + 1) * WTOT + jstart + row];
      }
      __nv_bfloat16 h0, l0, h1, l1;
      bsplit(x0, h0, l0); bsplit(x1, h1, l1);
      g_W2hi[i] = pack2(h0, h1);
      g_W2lo[i] = pack2(l0, l1);
    } else {
      int r = i - NCHUNK * T2W;
      int row = r / 68, kp = r % 68;
      float x0 = 0.f, x1 = 0.f;
      if (kp < 64) {
        x0 = W1[(size_t)(2 * kp) * 128 + row];
        x1 = W1[(size_t)(2 * kp + 1) * 128 + row];
      }
      __nv_bfloat16 h0, l0, h1, l1;
      bsplit(x0, h0, l0); bsplit(x1, h1, l1);
      g_W1hi[r] = pack2(h0, h1);
      g_W1lo[r] = pack2(l0, l1);
    }
  }
}

// ---------------- K1: HMMA h = relu(edge_attr @ W1 + b1) -> bf16 hi/lo A tiles ------
// M=64 edges per block, 256 threads, 2 CTAs/SM.
static constexpr int K1_AHI = 0;
static constexpr int K1_ALO = T64B;            // 17408
static constexpr int K1_BHI = 2 * T64B;        // 34816 (128-row W1 tile)
static constexpr int K1_BLO = K1_BHI + T128B;  // 69632
static constexpr int K1_MBAR = K1_BLO + T128B; // 104448
static constexpr int K1_SMEM = K1_MBAR + 16;

__global__ __launch_bounds__(256, 2) void k_gemm1(const float* __restrict__ A,
                                                  const float* __restrict__ b1) {
  extern __shared__ char smem[];
  char* sAhi = smem;
  char* sAlo = smem + K1_ALO;
  uint32_t sb = smem_u32(smem);
  uint32_t mbar = sb + K1_MBAR;

  int tid = threadIdx.x;
  int wid = tid >> 5, lane = tid & 31;
  int blk = blockIdx.x;
  int e0 = blk * TB;

  if (tid == 0) {
    mbar_init(mbar, 1);
    fence_proxy_async_cta();
    mbar_expect_tx(mbar, 2 * T128B);
    bulk_cp(sb + K1_BHI, g_W1hi, T128B, mbar);
    bulk_cp(sb + K1_BLO, g_W1lo, T128B, mbar);
  }

  // A tiles: load edge_attr fp32 (coalesced), split, store pitch-68
  for (int i = tid; i < 64 * 64; i += 256) {
    int e = i >> 6, kp = i & 63;
    float2 x = make_float2(0.f, 0.f);
    if (e0 + e < NEDGE) x = *(const float2*)&A[(size_t)(e0 + e) * 128 + 2 * kp];
    __nv_bfloat16 h0, l0, h1, l1;
    bsplit(x.x, h0, l0); bsplit(x.y, h1, l1);
    uint32_t off = toff(e, kp);
    *(uint32_t*)(sAhi + off) = pack2(h0, h1);
    *(uint32_t*)(sAlo + off) = pack2(l0, l1);
  }
  mbar_wait(mbar, 0);
  __syncthreads();

  // warp grid: 2(m) x 4(n), each warp 32x32 of the 64x128 C
  int m0 = (wid >> 2) * 32, n0 = (wid & 3) * 32;
  int g = lane >> 2, t = lane & 3;
  int lane15 = lane & 15;
  int khalf4 = (lane >> 4) << 2;

  float acc[2][4][4];
#pragma unroll
  for (int mi = 0; mi < 2; ++mi)
#pragma unroll
    for (int ni = 0; ni < 4; ++ni)
#pragma unroll
      for (int r = 0; r < 4; ++r) acc[mi][ni][r] = 0.f;

#pragma unroll
  for (int pass = 0; pass < 3; ++pass) {
    uint32_t pa = sb + ((pass == 2) ? K1_ALO : K1_AHI);
    uint32_t pb = sb + ((pass == 1) ? K1_BLO : K1_BHI);
    uint32_t aAd0 = pa + toff(m0 + lane15, khalf4);
    uint32_t aAd1 = aAd0 + 16 * 272;
    uint32_t bAd0 = pb + toff(n0 + lane15, khalf4);
    uint32_t bAd1 = bAd0 + 16 * 272;
#pragma unroll
    for (int ks = 0; ks < 8; ++ks) {
      uint32_t ko = (uint32_t)ks * 32;
      uint32_t a0[4], a1[4], b00, b01, b02, b03, b10, b11, b12, b13;
      ldsm4(a0[0], a0[1], a0[2], a0[3], aAd0 + ko);
      ldsm4(a1[0], a1[1], a1[2], a1[3], aAd1 + ko);
      ldsm4(b00, b01, b02, b03, bAd0 + ko);
      ldsm4(b10, b11, b12, b13, bAd1 + ko);
      mma16816(acc[0][0], a0, b00, b02);
      mma16816(acc[0][1], a0, b01, b03);
      mma16816(acc[0][2], a0, b10, b12);
      mma16816(acc[0][3], a0, b11, b13);
      mma16816(acc[1][0], a1, b00, b02);
      mma16816(acc[1][1], a1, b01, b03);
      mma16816(acc[1][2], a1, b10, b12);
      mma16816(acc[1][3], a1, b11, b13);
    }
  }
  __syncthreads();   // done reading A tiles; reuse sAhi/sAlo as export staging

  // epilogue: +bias, relu, split -> smem (pitch 68), then coalesced export
#pragma unroll
  for (int ni = 0; ni < 4; ++ni) {
    int c0 = n0 + ni * 8 + 2 * t;
    int kp = c0 >> 1;
    float bx = b1[c0], by = b1[c0 + 1];
#pragma unroll
    for (int mi = 0; mi < 2; ++mi) {
      int row = m0 + mi * 16 + g;
      float v0 = fmaxf(acc[mi][ni][0] + bx, 0.f);
      float v1 = fmaxf(acc[mi][ni][1] + by, 0.f);
      float v2 = fmaxf(acc[mi][ni][2] + bx, 0.f);
      float v3 = fmaxf(acc[mi][ni][3] + by, 0.f);
      __nv_bfloat16 h0, l0, h1, l1;
      bsplit(v0, h0, l0); bsplit(v1, h1, l1);
      *(uint32_t*)(sAhi + toff(row, kp)) = pack2(h0, h1);
      *(uint32_t*)(sAlo + toff(row, kp)) = pack2(l0, l1);
      bsplit(v2, h0, l0); bsplit(v3, h1, l1);
      *(uint32_t*)(sAhi + toff(row + 8, kp)) = pack2(h0, h1);
      *(uint32_t*)(sAlo + toff(row + 8, kp)) = pack2(l0, l1);
    }
  }
  __syncthreads();

  uint4* dsthi = (uint4*)(g_Ahi + (size_t)blk * T2W);
  uint4* dstlo = (uint4*)(g_Alo + (size_t)blk * T2W);
  for (int i = tid; i < T64B / 16; i += 256) {
    dsthi[i] = *(const uint4*)(sAhi + i * 16);
    dstlo[i] = *(const uint4*)(sAlo + i * 16);
  }
}

// ---------------- K2: fused HMMA GEMM2 (bf16x3) + tensor product + scatter --------
// 64 edges / 256 threads / 2 CTAs per SM.  smem ~93.5 KB per CTA.
static constexpr int SM_AHI  = 0;
static constexpr int SM_ALO  = T64B;                    // 17408
static constexpr int SM_BHI  = 2 * T64B;                // 34816 (also sC staging)
static constexpr int SM_BLO  = 3 * T64B;                // 52224
static constexpr int SM_TPF  = 4 * T64B;                // 69632
static constexpr int FS_S    = SM_TPF / 4;              // 64*48
static constexpr int FS_DOT  = FS_S + 64 * 48;
static constexpr int FS_VIN  = FS_DOT + 64 * 10;
static constexpr int FS_SH   = FS_VIN + 64 * 30;
static constexpr int SM_BIAS = (FS_SH + 64 * 4) * 4;    // 93184
static constexpr int SM_MBAR = SM_BIAS + 256;           // 93440
static constexpr int K2_SMEM = SM_MBAR + 16;            // 93456

__global__ __launch_bounds__(256, 2) void k_fused(const int* __restrict__ eidx,
                                                  const float* __restrict__ node_attr,
                                                  const float* __restrict__ edge_sh,
                                                  const float* __restrict__ b2) {
  extern __shared__ char smem[];
  float* smf   = (float*)smem;
  float* sC    = (float*)(smem + SM_BHI);   // C staging, pitch 68 floats (overlays B_hi)
  float* sS    = smf + FS_S;
  float* sDot  = smf + FS_DOT;
  float* sVin  = smf + FS_VIN;
  float* sSh   = smf + FS_SH;
  float* sBias = (float*)(smem + SM_BIAS);
  uint32_t sb = smem_u32(smem);
  uint32_t mbar = sb + SM_MBAR;

  int tid = threadIdx.x;
  int wid = tid >> 5, lane = tid & 31;
  int blk = blockIdx.x;
  int e0 = blk * TB;

  // phase 0: A tiles + B chunk 0
  if (tid == 0) {
    mbar_init(mbar, 1);
    fence_proxy_async_cta();
    mbar_expect_tx(mbar, 4 * T64B);
    bulk_cp(sb + SM_AHI, g_Ahi + (size_t)blk * T2W, T64B, mbar);
    bulk_cp(sb + SM_ALO, g_Alo + (size_t)blk * T2W, T64B, mbar);
    bulk_cp(sb + SM_BHI, g_W2hi, T64B, mbar);
    bulk_cp(sb + SM_BLO, g_W2lo, T64B, mbar);
  }

  int e_ = tid >> 2, q = tid & 3;   // 4 owner threads per edge (64 edges)

  // register accumulators
  float rAc0[12];
#pragma unroll
  for (int i = 0; i < 12; ++i) rAc0[i] = 0.f;
  float rYa[3] = {0.f, 0.f, 0.f};
  float rYb[3][3];
#pragma unroll
  for (int i = 0; i < 3; ++i)
#pragma unroll
    for (int j = 0; j < 3; ++j) rYb[i][j] = 0.f;

  // left vectors (overlap bulk copies)
  {
    int eg = e0 + e_;
    if (eg < NEDGE) {
      int dst = eidx[NEDGE + eg];
      const float* x = node_attr + (size_t)dst * 78;
      for (int u = q * 12; u < q * 12 + 12; ++u) sS[e_ * 48 + u] = x[u];
      for (int m = q; m < 30; m += 4) sVin[e_ * 30 + m] = x[48 + m];
      if (q == 0)
        for (int i = 0; i < 4; ++i) sSh[e_ * 4 + i] = edge_sh[(size_t)eg * 4 + i];
    }
  }
  __syncthreads();
  {
    float s1 = sSh[e_ * 4 + 1], s2 = sSh[e_ * 4 + 2], s3 = sSh[e_ * 4 + 3];
    for (int u = q; u < 10; u += 4)
      sDot[e_ * 10 + u] = (sVin[e_ * 30 + u * 3] * s1 + sVin[e_ * 30 + u * 3 + 1] * s2 +
                           sVin[e_ * 30 + u * 3 + 2] * s3) * INV_SQRT3;
  }

  // warp grid: 2(m) x 4(n), each warp 32x16 of the 64x64 C
  int m0 = (wid >> 2) * 32, n0 = (wid & 3) * 16;
  int g = lane >> 2, t = lane & 3;
  int lane15 = lane & 15;
  int khalf4 = (lane >> 4) << 2;

  for (int ci = 0; ci < NCHUNK; ++ci) {
    int type, jstart, cnt, rel;
    chunk_params(ci, type, jstart, cnt, rel);

    if (ci > 0) {
      __syncthreads();   // prior epilogue done with sC before overwriting B region
      if (tid == 0) {
        fence_proxy_async_cta();
        mbar_expect_tx(mbar, 2 * T64B);
        bulk_cp(sb + SM_BHI, g_W2hi + (size_t)ci * T2W, T64B, mbar);
        bulk_cp(sb + SM_BLO, g_W2lo + (size_t)ci * T2W, T64B, mbar);
      }
    }
    if (tid < 64) sBias[tid] = (tid < cnt) ? b2[jstart + tid] : 0.f;
    mbar_wait(mbar, (uint32_t)(ci & 1));
    __syncthreads();

    // ---- 3-pass HMMA via ldmatrix ----
    float acc[2][2][4];
#pragma unroll
    for (int mi = 0; mi < 2; ++mi)
#pragma unroll
      for (int ni = 0; ni < 2; ++ni)
#pragma unroll
        for (int r = 0; r < 4; ++r) acc[mi][ni][r] = 0.f;

#pragma unroll
    for (int pass = 0; pass < 3; ++pass) {
      uint32_t pa = sb + ((pass == 2) ? SM_ALO : SM_AHI);
      uint32_t pb = sb + ((pass == 1) ? SM_BLO : SM_BHI);
      uint32_t aAd0 = pa + toff(m0 + lane15, khalf4);
      uint32_t aAd1 = aAd0 + 16 * 272;
      uint32_t bAd  = pb + toff(n0 + lane15, khalf4);
#pragma unroll
      for (int ks = 0; ks < 8; ++ks) {
        uint32_t ko = (uint32_t)ks * 32;
        uint32_t a0[4], a1[4], b0, b1, b2v, b3;
        ldsm4(a0[0], a0[1], a0[2], a0[3], aAd0 + ko);
        ldsm4(a1[0], a1[1], a1[2], a1[3], aAd1 + ko);
        ldsm4(b0, b1, b2v, b3, bAd + ko);
        mma16816(acc[0][0], a0, b0, b2v);
        mma16816(acc[0][1], a0, b1, b3);
        mma16816(acc[1][0], a1, b0, b2v);
        mma16816(acc[1][1], a1, b1, b3);
      }
    }
    __syncthreads();   // all MMA reads of sB done before sC overwrite

    // ---- C fragments + bias -> sC staging (pitch 68 floats) ----
#pragma unroll
    for (int mi = 0; mi < 2; ++mi) {
      int row = m0 + mi * 16 + g;
#pragma unroll
      for (int ni = 0; ni < 2; ++ni) {
        int col = n0 + ni * 8 + 2 * t;
        float bx = sBias[col], by = sBias[col + 1];
        *(float2*)&sC[row * 68 + col] =
            make_float2(acc[mi][ni][0] + bx, acc[mi][ni][1] + by);
        *(float2*)&sC[(row + 8) * 68 + col] =
            make_float2(acc[mi][ni][2] + bx, acc[mi][ni][3] + by);
      }
    }
    __syncthreads();   // sC complete

    // ---- ownership-partitioned banded TP epilogue ----
    if (type == 1 || type == 4) {
      const float* mult = (type == 1) ? (sS + e_ * 48) : (sDot + e_ * 10);
      int umax = (type == 1) ? 47 : 9;
      const float* Cs = sC + e_ * 68 - rel;
#pragma unroll 4
      for (int vv = 0; vv < 12; ++vv) {
        int v = q * 12 + vv;
        int d = rel - v;
        int u0 = d > 0 ? (d + 47) / 48 : 0;
        int u1 = (rel + cnt - 1 - v) / 48; if (u1 > umax) u1 = umax;
        float p = 0.f;
        for (int u = u0; u <= u1; ++u) p = fmaf(Cs[u * 48 + v], mult[u], p);
        rAc0[vv] += p;
      }
    } else if (type == 2) {
      const float* Cs = sC + e_ * 68 - rel;
#pragma unroll
      for (int i = 0; i < 3; ++i) {
        int v = q + 4 * i;
        if (v < 10) {
          int d = rel - v;
          int u0 = d > 0 ? (d + 9) / 10 : 0;
          int u1 = (rel + cnt - 1 - v) / 10; if (u1 > 47) u1 = 47;
          float p = 0.f;
          for (int u = u0; u <= u1; ++u) p = fmaf(Cs[u * 10 + v], sS[e_ * 48 + u], p);
          rYa[i] += p;
        }
      }
    } else {  // w3, banded over sub-chunk
      const float* Cs = sC + e_ * 68 - rel;
#pragma unroll
      for (int i = 0; i < 3; ++i) {
        int v = q + 4 * i;
        if (v < 10) {
          int d = rel - v;
          int u0 = d > 0 ? (d + 9) / 10 : 0;
          int u1 = (rel + cnt - 1 - v) / 10; if (u1 > 9) u1 = 9;
          float y0 = 0.f, y1 = 0.f, y2 = 0.f;
          for (int u = u0; u <= u1; ++u) {
            float wv = Cs[u * 10 + v];
            y0 = fmaf(wv, sVin[e_ * 30 + u * 3 + 0], y0);
            y1 = fmaf(wv, sVin[e_ * 30 + u * 3 + 1], y1);
            y2 = fmaf(wv, sVin[e_ * 30 + u * 3 + 2], y2);
          }
          rYb[i][0] += y0; rYb[i][1] += y1; rYb[i][2] += y2;
        }
      }
    }

    if (ci == 7) {  // w2 phase done -> scale s by sh0 for the w1 phase
      __syncthreads();
      float s0 = sSh[e_ * 4 + 0];
      for (int vv = 0; vv < 12; ++vv) sS[e_ * 48 + q * 12 + vv] *= s0;
    }
  }
  __syncthreads();

  // ---- final per-edge output + scatter to node sums ----
  {
    int eg = e0 + e_;
    if (eg < NEDGE) {
      int src = eidx[eg];
      float s0 = sSh[e_ * 4], s1 = sSh[e_ * 4 + 1], s2 = sSh[e_ * 4 + 2], s3 = sSh[e_ * 4 + 3];
      float* dp = g_sum + (size_t)src * 78;
#pragma unroll
      for (int vv = 0; vv < 12; ++vv) {
        int v = q * 12 + vv;
        atomicAdd(&dp[v], rAc0[vv] * NORM01);
      }
#pragma unroll
      for (int i = 0; i < 3; ++i) {
        int v = q + 4 * i;
        if (v < 10) {
          atomicAdd(&dp[48 + v * 3 + 0], (rYa[i] * s1 + rYb[i][0] * s0) * NORM01);
          atomicAdd(&dp[48 + v * 3 + 1], (rYa[i] * s2 + rYb[i][1] * s0) * NORM01);
          atomicAdd(&dp[48 + v * 3 + 2], (rYa[i] * s3 + rYb[i][2] * s0) * NORM01);
        }
      }
      if (q == 0) atomicAdd(&g_cnt[src], 1.f);
    }
  }
}

// ---------------- K3: node finalize (mean + residual) + BN statistics ----------------
__global__ __launch_bounds__(256) void k_node(const float* __restrict__ node_attr,
                                              float* __restrict__ dout) {
  __shared__ float sP[106];
  int tid = threadIdx.x;
  if (tid < 106) sP[tid] = 0.f;
  __syncthreads();

  int n = blockIdx.x * blockDim.x + tid;
  bool valid = n < NNODE;
  float inv = 1.f;
  if (valid) inv = 1.f / fmaxf(g_cnt[n], 1.f);
  const float* srow  = g_sum + (valid ? (size_t)n * 78 : 0);
  const float* narow = node_attr + (valid ? (size_t)n * 78 : 0);

  for (int v = 0; v < 48; ++v) {
    float val = 0.f;
    if (valid) { val = srow[v] * inv + narow[v]; dout[(size_t)n * 78 + v] = val; }
    float s = val, qq = val * val;
#pragma unroll
    for (int o = 16; o; o >>= 1) {
      s += __shfl_xor_sync(0xffffffffu, s, o);
      qq += __shfl_xor_sync(0xffffffffu, qq, o);
    }
    if ((tid & 31) == 0) { atomicAdd(&sP[v], s); atomicAdd(&sP[48 + v], qq); }
  }
  for (int u = 0; u < 10; ++u) {
    float qq = 0.f;
    for (int i = 0; i < 3; ++i) {
      float val = 0.f;
      int c = 48 + u * 3 + i;
      if (valid) { val = srow[c] * inv + narow[c]; dout[(size_t)n * 78 + c] = val; }
      qq += val * val;
    }
#pragma unroll
    for (int o = 16; o; o >>= 1) qq += __shfl_xor_sync(0xffffffffu, qq, o);
    if ((tid & 31) == 0) atomicAdd(&sP[96 + u], qq);
  }
  __syncthreads();
  if (tid < 106) atomicAdd(&g_stats[tid], sP[tid]);
}

// ---------------- K4: apply batch norm in place ----------------
__global__ void k_bn(const float* __restrict__ bnw, const float* __restrict__ bnb,
                     float* __restrict__ dout) {
  int idx = blockIdx.x * blockDim.x + threadIdx.x;
  if (idx >= NNODE * 78) return;
  int c = idx % 78;
  float x = dout[idx];
  if (c < 48) {
    float mean = g_stats[c] * (1.f / NNODE);
    float var  = g_stats[48 + c] * (1.f / NNODE) - mean * mean;
    dout[idx] = (x - mean) * rsqrtf(var + EPS_BN) * bnw[c] + bnb[c];
  } else {
    int u = (c - 48) / 3;
    float vn = g_stats[96 + u] * (1.f / (3.f * NNODE));
    dout[idx] = x * rsqrtf(vn + EPS_BN) * bnw[48 + u];
  }
}

// ---------------- launch ----------------
extern "C" void kernel_launch(void* const* d_in, const int* in_sizes, int n_in,
                              void* d_out, int out_size) {
  const float* node_attr  = (const float*)d_in[0];
  const int*   edge_index = (const int*)d_in[1];
  const float* edge_attr  = (const float*)d_in[2];
  const float* edge_sh    = (const float*)d_in[3];
  const float* fc_w1      = (const float*)d_in[4];
  const float* fc_b1      = (const float*)d_in[5];
  const float* fc_w2      = (const float*)d_in[6];
  const float* fc_b2      = (const float*)d_in[7];
  const float* bn_w       = (const float*)d_in[8];
  const float* bn_b       = (const float*)d_in[9];
  float* out = (float*)d_out;

  cudaFuncSetAttribute(k_gemm1, cudaFuncAttributeMaxDynamicSharedMemorySize, K1_SMEM);
  cudaFuncSetAttribute(k_fused, cudaFuncAttributeMaxDynamicSharedMemorySize, K2_SMEM);

  k_zero<<<256, 256>>>();
  k_prep<<<480, 512>>>(fc_w1, fc_w2);
  k_gemm1<<<NBLK, 256, K1_SMEM>>>(edge_attr, fc_b1);
  k_fused<<<NBLK, 256, K2_SMEM>>>(edge_index, node_attr, edge_sh, fc_b2);
  k_node<<<(NNODE + 255) / 256, 256>>>(node_attr, out);
  k_bn<<<(NNODE * 78 + 255) / 256, 256>>>(bn_w, bn_b, out);
}

// round 15
// speedup vs baseline: 1.5658x; 1.0710x over previous
#include <cuda_runtime.h>
#include <cuda_bf16.h>
#include <cuda_fp16.h>
#include <cstdint>

// ---------------- problem constants ----------------
static constexpr int NNODE = 10000;
static constexpr int NEDGE = 50000;
static constexpr int WTOT  = 3364;  // 2304 + 480 + 100 + 480
static constexpr int OFF2  = 2304;
static constexpr int OFF3  = 2784;
static constexpr int OFF4  = 2884;
static constexpr int TB    = 64;                       // edges per tile
static constexpr int NBLK  = (NEDGE + TB - 1) / TB;    // 782
static constexpr int NCHUNK = 54;                      // N=64 sub-chunks
static constexpr int T2W   = 64 * 68;                  // words per 64-row tile (4352)
static constexpr int T1W   = 128 * 68;                 // words per 128-row tile (8704)
static constexpr int T64B  = T2W * 4;                  // 17408 bytes
static constexpr int T128B = T1W * 4;                  // 34816 bytes

#define EPS_BN     1e-5f
#define INV_SQRT3  0.57735026918962576f
#define NORM01     0.13130643285972254f   /* 1/sqrt(58) */

// ---------------- mma.sync / ldmatrix helpers (compile for sm_103) ----------
__device__ __forceinline__ void mma_bf16(float* c, const uint32_t* a,
                                         uint32_t b0, uint32_t b1) {
  asm volatile(
      "mma.sync.aligned.m16n8k16.row.col.f32.bf16.bf16.f32 "
      "{%0,%1,%2,%3}, {%4,%5,%6,%7}, {%8,%9}, {%0,%1,%2,%3};"
      : "+f"(c[0]), "+f"(c[1]), "+f"(c[2]), "+f"(c[3])
      : "r"(a[0]), "r"(a[1]), "r"(a[2]), "r"(a[3]), "r"(b0), "r"(b1));
}
__device__ __forceinline__ void mma_f16(float* c, const uint32_t* a,
                                        uint32_t b0, uint32_t b1) {
  asm volatile(
      "mma.sync.aligned.m16n8k16.row.col.f32.f16.f16.f32 "
      "{%0,%1,%2,%3}, {%4,%5,%6,%7}, {%8,%9}, {%0,%1,%2,%3};"
      : "+f"(c[0]), "+f"(c[1]), "+f"(c[2]), "+f"(c[3])
      : "r"(a[0]), "r"(a[1]), "r"(a[2]), "r"(a[3]), "r"(b0), "r"(b1));
}
__device__ __forceinline__ void ldsm4(uint32_t& r0, uint32_t& r1, uint32_t& r2,
                                      uint32_t& r3, uint32_t addr) {
  asm volatile("ldmatrix.sync.aligned.m8n8.x4.shared.b16 {%0,%1,%2,%3}, [%4];"
               : "=r"(r0), "=r"(r1), "=r"(r2), "=r"(r3) : "r"(addr));
}

// smem tile: row-major, 64 k-words (16-bit x2)/row, pitch 68 words (272 B).
// pitch 68 => 4-bank shift per row => conflict-free ldmatrix + builds.
__device__ __forceinline__ uint32_t toff(int row, int kp) {
  return (uint32_t)(row * 68 + kp) * 4u;
}

// bf16 hi/lo split (GEMM1)
__device__ __forceinline__ void bsplit(float x, __nv_bfloat16& hi, __nv_bfloat16& lo) {
  hi = __float2bfloat16(x);
  lo = __float2bfloat16(x - __bfloat162float(hi));
}
__device__ __forceinline__ uint32_t pack2b(__nv_bfloat16 a, __nv_bfloat16 b) {
  __nv_bfloat162 v; v.x = a; v.y = b;
  return *(uint32_t*)&v;
}
// fp16 hi/lo split (GEMM2 A) and single fp16 (GEMM2 B)
__device__ __forceinline__ void hsplit(float x, __half& hi, __half& lo) {
  hi = __float2half_rn(x);
  lo = __float2half_rn(x - __half2float(hi));
}
__device__ __forceinline__ uint32_t pack2h(__half a, __half b) {
  __half2 v; v.x = a; v.y = b;
  return *(uint32_t*)&v;
}

// ---------------- async bulk copy + mbarrier helpers ----------------
__device__ __forceinline__ uint32_t smem_u32(const void* p) {
  uint32_t a;
  asm("{ .reg .u64 t; cvta.to.shared.u64 t, %1; cvt.u32.u64 %0, t; }" : "=r"(a) : "l"(p));
  return a;
}
__device__ __forceinline__ void mbar_init(uint32_t mbar, uint32_t cnt) {
  asm volatile("mbarrier.init.shared.b64 [%0], %1;" :: "r"(mbar), "r"(cnt) : "memory");
}
__device__ __forceinline__ void mbar_expect_tx(uint32_t mbar, uint32_t bytes) {
  asm volatile("mbarrier.arrive.expect_tx.shared.b64 _, [%0], %1;"
               :: "r"(mbar), "r"(bytes) : "memory");
}
__device__ __forceinline__ void mbar_wait(uint32_t mbar, uint32_t parity) {
  asm volatile(
      "{\n\t.reg .pred P;\n\t"
      "WL_%=:\n\t"
      "mbarrier.try_wait.parity.acquire.cta.shared::cta.b64 P, [%0], %1, 0x989680;\n\t"
      "@P bra.uni WD_%=;\n\t"
      "bra.uni WL_%=;\n\t"
      "WD_%=:\n\t}"
      :: "r"(mbar), "r"(parity) : "memory");
}
__device__ __forceinline__ void bulk_cp(uint32_t dst, const void* src,
                                        uint32_t bytes, uint32_t mbar) {
  asm volatile(
      "cp.async.bulk.shared::cluster.global.mbarrier::complete_tx::bytes [%0], [%1], %2, [%3];"
      :: "r"(dst), "l"(src), "r"(bytes), "r"(mbar) : "memory");
}
__device__ __forceinline__ void fence_proxy_async_cta() {
  asm volatile("fence.proxy.async.shared::cta;" ::: "memory");
}

// chunk schedule: 8x w2 -> 36x w1 -> 8x w4 -> 2x w3, all N<=64
__device__ __forceinline__ void chunk_params(int ci, int& type, int& jstart,
                                             int& cnt, int& rel) {
  if (ci < 8)       { type = 2; rel = ci * 64;        cnt = (rel + 64 <= 480) ? 64 : 480 - rel; jstart = OFF2 + rel; }
  else if (ci < 44) { type = 1; rel = (ci - 8) * 64;  cnt = 64;                                  jstart = rel; }
  else if (ci < 52) { type = 4; rel = (ci - 44) * 64; cnt = (rel + 64 <= 480) ? 64 : 480 - rel;  jstart = OFF4 + rel; }
  else              { type = 3; rel = (ci - 52) * 64; cnt = (rel + 64 <= 100) ? 64 : 100 - rel;  jstart = OFF3 + rel; }
}

// ---------------- scratch (global byte-images of smem tiles, pitch 68) ------------
__device__ __align__(256) uint32_t g_Ahi[(size_t)NBLK * T2W];   // fp16 hi tiles of relu(h)
__device__ __align__(256) uint32_t g_Alo[(size_t)NBLK * T2W];   // fp16 lo tiles
__device__ __align__(256) uint32_t g_W2h[(size_t)NCHUNK * T2W]; // W2^T chunk tiles (fp16)
__device__ __align__(256) uint32_t g_W1hi[T1W];                 // W1^T bf16 hi
__device__ __align__(256) uint32_t g_W1lo[T1W];                 // W1^T bf16 lo
__device__ float g_sum[(size_t)NNODE * 78];
__device__ float g_cnt[NNODE];
__device__ float g_stats[106];

// ---------------- K0: zero scratch ----------------
__global__ void k_zero() {
  int idx = blockIdx.x * blockDim.x + threadIdx.x;
  int stride = gridDim.x * blockDim.x;
  for (int i = idx; i < NNODE * 78; i += stride) g_sum[i] = 0.f;
  for (int i = idx; i < NNODE; i += stride) g_cnt[i] = 0.f;
  if (idx < 106) g_stats[idx] = 0.f;
}

// ---------------- Kp: pre-convert W2 -> fp16 tiles, W1 -> bf16 hi/lo tiles ----------
__global__ void k_prep(const float* __restrict__ W1, const float* __restrict__ W2) {
  int idx = blockIdx.x * blockDim.x + threadIdx.x;
  int stride = gridDim.x * blockDim.x;
  int total = NCHUNK * T2W + T1W;
  for (int i = idx; i < total; i += stride) {
    if (i < NCHUNK * T2W) {
      int tile = i / T2W;
      int r = i - tile * T2W;
      int row = r / 68, kp = r % 68;
      int type, jstart, cnt, rel;
      chunk_params(tile, type, jstart, cnt, rel);
      float x0 = 0.f, x1 = 0.f;
      if (kp < 64 && row < cnt) {
        x0 = W2[(size_t)(2 * kp) * WTOT + jstart + row];
        x1 = W2[(size_t)(2 * kp + 1) * WTOT + jstart + row];
      }
      g_W2h[i] = pack2h(__float2half_rn(x0), __float2half_rn(x1));
    } else {
      int r = i - NCHUNK * T2W;
      int row = r / 68, kp = r % 68;
      float x0 = 0.f, x1 = 0.f;
      if (kp < 64) {
        x0 = W1[(size_t)(2 * kp) * 128 + row];
        x1 = W1[(size_t)(2 * kp + 1) * 128 + row];
      }
      __nv_bfloat16 h0, l0, h1, l1;
      bsplit(x0, h0, l0); bsplit(x1, h1, l1);
      g_W1hi[r] = pack2b(h0, h1);
      g_W1lo[r] = pack2b(l0, l1);
    }
  }
}

// ---------------- K1: HMMA h = relu(edge_attr @ W1 + b1) -> fp16 hi/lo A tiles ------
// M=64 edges per block, 256 threads, 2 CTAs/SM.  (bf16 x3 compute, fp16 export)
static constexpr int K1_AHI = 0;
static constexpr int K1_ALO = T64B;            // 17408
static constexpr int K1_BHI = 2 * T64B;        // 34816 (128-row W1 tile)
static constexpr int K1_BLO = K1_BHI + T128B;  // 69632
static constexpr int K1_MBAR = K1_BLO + T128B; // 104448
static constexpr int K1_SMEM = K1_MBAR + 16;

__global__ __launch_bounds__(256, 2) void k_gemm1(const float* __restrict__ A,
                                                  const float* __restrict__ b1) {
  extern __shared__ char smem[];
  char* sAhi = smem;
  char* sAlo = smem + K1_ALO;
  uint32_t sb = smem_u32(smem);
  uint32_t mbar = sb + K1_MBAR;

  int tid = threadIdx.x;
  int wid = tid >> 5, lane = tid & 31;
  int blk = blockIdx.x;
  int e0 = blk * TB;

  if (tid == 0) {
    mbar_init(mbar, 1);
    fence_proxy_async_cta();
    mbar_expect_tx(mbar, 2 * T128B);
    bulk_cp(sb + K1_BHI, g_W1hi, T128B, mbar);
    bulk_cp(sb + K1_BLO, g_W1lo, T128B, mbar);
  }

  // A tiles: load edge_attr fp32 (coalesced), split bf16, store pitch-68
  for (int i = tid; i < 64 * 64; i += 256) {
    int e = i >> 6, kp = i & 63;
    float2 x = make_float2(0.f, 0.f);
    if (e0 + e < NEDGE) x = *(const float2*)&A[(size_t)(e0 + e) * 128 + 2 * kp];
    __nv_bfloat16 h0, l0, h1, l1;
    bsplit(x.x, h0, l0); bsplit(x.y, h1, l1);
    uint32_t off = toff(e, kp);
    *(uint32_t*)(sAhi + off) = pack2b(h0, h1);
    *(uint32_t*)(sAlo + off) = pack2b(l0, l1);
  }
  mbar_wait(mbar, 0);
  __syncthreads();

  // warp grid: 2(m) x 4(n), each warp 32x32 of the 64x128 C
  int m0 = (wid >> 2) * 32, n0 = (wid & 3) * 32;
  int g = lane >> 2, t = lane & 3;
  int lane15 = lane & 15;
  int khalf4 = (lane >> 4) << 2;

  float acc[2][4][4];
#pragma unroll
  for (int mi = 0; mi < 2; ++mi)
#pragma unroll
    for (int ni = 0; ni < 4; ++ni)
#pragma unroll
      for (int r = 0; r < 4; ++r) acc[mi][ni][r] = 0.f;

#pragma unroll
  for (int pass = 0; pass < 3; ++pass) {
    uint32_t pa = sb + ((pass == 2) ? K1_ALO : K1_AHI);
    uint32_t pb = sb + ((pass == 1) ? K1_BLO : K1_BHI);
    uint32_t aAd0 = pa + toff(m0 + lane15, khalf4);
    uint32_t aAd1 = aAd0 + 16 * 272;
    uint32_t bAd0 = pb + toff(n0 + lane15, khalf4);
    uint32_t bAd1 = bAd0 + 16 * 272;
#pragma unroll
    for (int ks = 0; ks < 8; ++ks) {
      uint32_t ko = (uint32_t)ks * 32;
      uint32_t a0[4], a1[4], b00, b01, b02, b03, b10, b11, b12, b13;
      ldsm4(a0[0], a0[1], a0[2], a0[3], aAd0 + ko);
      ldsm4(a1[0], a1[1], a1[2], a1[3], aAd1 + ko);
      ldsm4(b00, b01, b02, b03, bAd0 + ko);
      ldsm4(b10, b11, b12, b13, bAd1 + ko);
      mma_bf16(acc[0][0], a0, b00, b02);
      mma_bf16(acc[0][1], a0, b01, b03);
      mma_bf16(acc[0][2], a0, b10, b12);
      mma_bf16(acc[0][3], a0, b11, b13);
      mma_bf16(acc[1][0], a1, b00, b02);
      mma_bf16(acc[1][1], a1, b01, b03);
      mma_bf16(acc[1][2], a1, b10, b12);
      mma_bf16(acc[1][3], a1, b11, b13);
    }
  }
  __syncthreads();   // done reading A tiles; reuse sAhi/sAlo as export staging

  // epilogue: +bias, relu, fp16 split -> smem (pitch 68), then coalesced export
#pragma unroll
  for (int ni = 0; ni < 4; ++ni) {
    int c0 = n0 + ni * 8 + 2 * t;
    int kp = c0 >> 1;
    float bx = b1[c0], by = b1[c0 + 1];
#pragma unroll
    for (int mi = 0; mi < 2; ++mi) {
      int row = m0 + mi * 16 + g;
      float v0 = fmaxf(acc[mi][ni][0] + bx, 0.f);
      float v1 = fmaxf(acc[mi][ni][1] + by, 0.f);
      float v2 = fmaxf(acc[mi][ni][2] + bx, 0.f);
      float v3 = fmaxf(acc[mi][ni][3] + by, 0.f);
      __half h0, l0, h1, l1;
      hsplit(v0, h0, l0); hsplit(v1, h1, l1);
      *(uint32_t*)(sAhi + toff(row, kp)) = pack2h(h0, h1);
      *(uint32_t*)(sAlo + toff(row, kp)) = pack2h(l0, l1);
      hsplit(v2, h0, l0); hsplit(v3, h1, l1);
      *(uint32_t*)(sAhi + toff(row + 8, kp)) = pack2h(h0, h1);
      *(uint32_t*)(sAlo + toff(row + 8, kp)) = pack2h(l0, l1);
    }
  }
  __syncthreads();

  uint4* dsthi = (uint4*)(g_Ahi + (size_t)blk * T2W);
  uint4* dstlo = (uint4*)(g_Alo + (size_t)blk * T2W);
  for (int i = tid; i < T64B / 16; i += 256) {
    dsthi[i] = *(const uint4*)(sAhi + i * 16);
    dstlo[i] = *(const uint4*)(sAlo + i * 16);
  }
}

// ---------------- K2: fused fp16x2 HMMA GEMM2 + tensor product + scatter --------
// 64 edges / 256 threads / 2 CTAs per SM.  Double-buffered B, dedicated sC.
static constexpr int SM_AHI  = 0;
static constexpr int SM_ALO  = T64B;                    // 17408
static constexpr int SM_B0   = 2 * T64B;                // 34816
static constexpr int SM_B1   = 3 * T64B;                // 52224
static constexpr int SM_SC   = 4 * T64B;                // 69632 (dedicated C staging)
static constexpr int SM_TPF  = 5 * T64B;                // 87040
static constexpr int FS_S    = SM_TPF / 4;              // 64*48
static constexpr int FS_DOT  = FS_S + 64 * 48;
static constexpr int FS_VIN  = FS_DOT + 64 * 10;
static constexpr int FS_SH   = FS_VIN + 64 * 30;
static constexpr int SM_BIAS = (FS_SH + 64 * 4) * 4;    // 110592
static constexpr int SM_MBAR = SM_BIAS + 256;           // 110848
static constexpr int K2_SMEM = SM_MBAR + 32;            // 110880

__global__ __launch_bounds__(256, 2) void k_fused(const int* __restrict__ eidx,
                                                  const float* __restrict__ node_attr,
                                                  const float* __restrict__ edge_sh,
                                                  const float* __restrict__ b2) {
  extern __shared__ char smem[];
  float* smf   = (float*)smem;
  float* sC    = (float*)(smem + SM_SC);    // pitch 68 floats
  float* sS    = smf + FS_S;
  float* sDot  = smf + FS_DOT;
  float* sVin  = smf + FS_VIN;
  float* sSh   = smf + FS_SH;
  float* sBias = (float*)(smem + SM_BIAS);
  uint32_t sb = smem_u32(smem);

  int tid = threadIdx.x;
  int wid = tid >> 5, lane = tid & 31;
  int blk = blockIdx.x;
  int e0 = blk * TB;

  // prologue: A tiles + B chunks 0,1 (double-buffered)
  if (tid == 0) {
    mbar_init(sb + SM_MBAR, 1);
    mbar_init(sb + SM_MBAR + 8, 1);
    fence_proxy_async_cta();
    mbar_expect_tx(sb + SM_MBAR, 3 * T64B);
    bulk_cp(sb + SM_AHI, g_Ahi + (size_t)blk * T2W, T64B, sb + SM_MBAR);
    bulk_cp(sb + SM_ALO, g_Alo + (size_t)blk * T2W, T64B, sb + SM_MBAR);
    bulk_cp(sb + SM_B0, g_W2h, T64B, sb + SM_MBAR);
    mbar_expect_tx(sb + SM_MBAR + 8, T64B);
    bulk_cp(sb + SM_B1, g_W2h + T2W, T64B, sb + SM_MBAR + 8);
  }

  int e_ = tid >> 2, q = tid & 3;   // 4 owner threads per edge (64 edges)

  // register accumulators
  float rAc0[12];
#pragma unroll
  for (int i = 0; i < 12; ++i) rAc0[i] = 0.f;
  float rYa[3] = {0.f, 0.f, 0.f};
  float rYb[3][3];
#pragma unroll
  for (int i = 0; i < 3; ++i)
#pragma unroll
    for (int j = 0; j < 3; ++j) rYb[i][j] = 0.f;

  // left vectors (overlap bulk copies)
  {
    int eg = e0 + e_;
    if (eg < NEDGE) {
      int dst = eidx[NEDGE + eg];
      const float* x = node_attr + (size_t)dst * 78;
      for (int u = q * 12; u < q * 12 + 12; ++u) sS[e_ * 48 + u] = x[u];
      for (int m = q; m < 30; m += 4) sVin[e_ * 30 + m] = x[48 + m];
      if (q == 0)
        for (int i = 0; i < 4; ++i) sSh[e_ * 4 + i] = edge_sh[(size_t)eg * 4 + i];
    }
  }
  __syncthreads();
  {
    float s1 = sSh[e_ * 4 + 1], s2 = sSh[e_ * 4 + 2], s3 = sSh[e_ * 4 + 3];
    for (int u = q; u < 10; u += 4)
      sDot[e_ * 10 + u] = (sVin[e_ * 30 + u * 3] * s1 + sVin[e_ * 30 + u * 3 + 1] * s2 +
                           sVin[e_ * 30 + u * 3 + 2] * s3) * INV_SQRT3;
  }

  // warp grid: 2(m) x 4(n), each warp 32x16 of the 64x64 C
  int m0 = (wid >> 2) * 32, n0 = (wid & 3) * 16;
  int g = lane >> 2, t = lane & 3;
  int lane15 = lane & 15;
  int khalf4 = (lane >> 4) << 2;

  for (int ci = 0; ci < NCHUNK; ++ci) {
    int type, jstart, cnt, rel;
    chunk_params(ci, type, jstart, cnt, rel);

    if (tid < 64) sBias[tid] = (tid < cnt) ? b2[jstart + tid] : 0.f;

    uint32_t mb = sb + SM_MBAR + 8 * (ci & 1);
    mbar_wait(mb, (uint32_t)((ci >> 1) & 1));

    // ---- 2-pass fp16 HMMA: acc = Ah*B + Al*B ----
    uint32_t pbB = sb + ((ci & 1) ? SM_B1 : SM_B0);
    float acc[2][2][4];
#pragma unroll
    for (int mi = 0; mi < 2; ++mi)
#pragma unroll
      for (int ni = 0; ni < 2; ++ni)
#pragma unroll
        for (int r = 0; r < 4; ++r) acc[mi][ni][r] = 0.f;

#pragma unroll
    for (int pass = 0; pass < 2; ++pass) {
      uint32_t pa = sb + ((pass == 1) ? SM_ALO : SM_AHI);
      uint32_t aAd0 = pa + toff(m0 + lane15, khalf4);
      uint32_t aAd1 = aAd0 + 16 * 272;
      uint32_t bAd  = pbB + toff(n0 + lane15, khalf4);
#pragma unroll
      for (int ks = 0; ks < 8; ++ks) {
        uint32_t ko = (uint32_t)ks * 32;
        uint32_t a0[4], a1[4], b0, b1, b2v, b3;
        ldsm4(a0[0], a0[1], a0[2], a0[3], aAd0 + ko);
        ldsm4(a1[0], a1[1], a1[2], a1[3], aAd1 + ko);
        ldsm4(b0, b1, b2v, b3, bAd + ko);
        mma_f16(acc[0][0], a0, b0, b2v);
        mma_f16(acc[0][1], a0, b1, b3);
        mma_f16(acc[1][0], a1, b0, b2v);
        mma_f16(acc[1][1], a1, b1, b3);
      }
    }
    __syncthreads();   // all warps done reading B buffer (ci&1) + bias written

    // prefetch B(ci+2) into the buffer just freed
    if (tid == 0 && ci + 2 < NCHUNK) {
      fence_proxy_async_cta();
      mbar_expect_tx(mb, T64B);
      bulk_cp(pbB, g_W2h + (size_t)(ci + 2) * T2W, T64B, mb);
    }

    // ---- C fragments + bias -> sC staging (pitch 68 floats) ----
#pragma unroll
    for (int mi = 0; mi < 2; ++mi) {
      int row = m0 + mi * 16 + g;
#pragma unroll
      for (int ni = 0; ni < 2; ++ni) {
        int col = n0 + ni * 8 + 2 * t;
        float bx = sBias[col], by = sBias[col + 1];
        *(float2*)&sC[row * 68 + col] =
            make_float2(acc[mi][ni][0] + bx, acc[mi][ni][1] + by);
        *(float2*)&sC[(row + 8) * 68 + col] =
            make_float2(acc[mi][ni][2] + bx, acc[mi][ni][3] + by);
      }
    }
    __syncthreads();   // sC complete

    // ---- ownership-partitioned banded TP epilogue ----
    if (type == 1 || type == 4) {
      const float* mult = (type == 1) ? (sS + e_ * 48) : (sDot + e_ * 10);
      int umax = (type == 1) ? 47 : 9;
      const float* Cs = sC + e_ * 68 - rel;
#pragma unroll 4
      for (int vv = 0; vv < 12; ++vv) {
        int v = q * 12 + vv;
        int d = rel - v;
        int u0 = d > 0 ? (d + 47) / 48 : 0;
        int u1 = (rel + cnt - 1 - v) / 48; if (u1 > umax) u1 = umax;
        float p = 0.f;
        for (int u = u0; u <= u1; ++u) p = fmaf(Cs[u * 48 + v], mult[u], p);
        rAc0[vv] += p;
      }
    } else if (type == 2) {
      const float* Cs = sC + e_ * 68 - rel;
#pragma unroll
      for (int i = 0; i < 3; ++i) {
        int v = q + 4 * i;
        if (v < 10) {
          int d = rel - v;
          int u0 = d > 0 ? (d + 9) / 10 : 0;
          int u1 = (rel + cnt - 1 - v) / 10; if (u1 > 47) u1 = 47;
          float p = 0.f;
          for (int u = u0; u <= u1; ++u) p = fmaf(Cs[u * 10 + v], sS[e_ * 48 + u], p);
          rYa[i] += p;
        }
      }
    } else {  // w3, banded over sub-chunk
      const float* Cs = sC + e_ * 68 - rel;
#pragma unroll
      for (int i = 0; i < 3; ++i) {
        int v = q + 4 * i;
        if (v < 10) {
          int d = rel - v;
          int u0 = d > 0 ? (d + 9) / 10 : 0;
          int u1 = (rel + cnt - 1 - v) / 10; if (u1 > 9) u1 = 9;
          float y0 = 0.f, y1 = 0.f, y2 = 0.f;
          for (int u = u0; u <= u1; ++u) {
            float wv = Cs[u * 10 + v];
            y0 = fmaf(wv, sVin[e_ * 30 + u * 3 + 0], y0);
            y1 = fmaf(wv, sVin[e_ * 30 + u * 3 + 1], y1);
            y2 = fmaf(wv, sVin[e_ * 30 + u * 3 + 2], y2);
          }
          rYb[i][0] += y0; rYb[i][1] += y1; rYb[i][2] += y2;
        }
      }
    }

    if (ci == 7) {  // w2 phase done -> scale s by sh0 for the w1 phase
      __syncthreads();  // all epilogue(7) reads of sS done
      float s0 = sSh[e_ * 4 + 0];
      for (int vv = 0; vv < 12; ++vv) sS[e_ * 48 + q * 12 + vv] *= s0;
      __syncthreads();  // scaled sS visible before epilogue(8)
    }
  }
  __syncthreads();

  // ---- final per-edge output + scatter to node sums ----
  {
    int eg = e0 + e_;
    if (eg < NEDGE) {
      int src = eidx[eg];
      float s0 = sSh[e_ * 4], s1 = sSh[e_ * 4 + 1], s2 = sSh[e_ * 4 + 2], s3 = sSh[e_ * 4 + 3];
      float* dp = g_sum + (size_t)src * 78;
#pragma unroll
      for (int vv = 0; vv < 12; ++vv) {
        int v = q * 12 + vv;
        atomicAdd(&dp[v], rAc0[vv] * NORM01);
      }
#pragma unroll
      for (int i = 0; i < 3; ++i) {
        int v = q + 4 * i;
        if (v < 10) {
          atomicAdd(&dp[48 + v * 3 + 0], (rYa[i] * s1 + rYb[i][0] * s0) * NORM01);
          atomicAdd(&dp[48 + v * 3 + 1], (rYa[i] * s2 + rYb[i][1] * s0) * NORM01);
          atomicAdd(&dp[48 + v * 3 + 2], (rYa[i] * s3 + rYb[i][2] * s0) * NORM01);
        }
      }
      if (q == 0) atomicAdd(&g_cnt[src], 1.f);
    }
  }
}

// ---------------- K3: node finalize (mean + residual) + BN statistics ----------------
__global__ __launch_bounds__(256) void k_node(const float* __restrict__ node_attr,
                                              float* __restrict__ dout) {
  __shared__ float sP[106];
  int tid = threadIdx.x;
  if (tid < 106) sP[tid] = 0.f;
  __syncthreads();

  int n = blockIdx.x * blockDim.x + tid;
  bool valid = n < NNODE;
  float inv = 1.f;
  if (valid) inv = 1.f / fmaxf(g_cnt[n], 1.f);
  const float* srow  = g_sum + (valid ? (size_t)n * 78 : 0);
  const float* narow = node_attr + (valid ? (size_t)n * 78 : 0);

  for (int v = 0; v < 48; ++v) {
    float val = 0.f;
    if (valid) { val = srow[v] * inv + narow[v]; dout[(size_t)n * 78 + v] = val; }
    float s = val, qq = val * val;
#pragma unroll
    for (int o = 16; o; o >>= 1) {
      s += __shfl_xor_sync(0xffffffffu, s, o);
      qq += __shfl_xor_sync(0xffffffffu, qq, o);
    }
    if ((tid & 31) == 0) { atomicAdd(&sP[v], s); atomicAdd(&sP[48 + v], qq); }
  }
  for (int u = 0; u < 10; ++u) {
    float qq = 0.f;
    for (int i = 0; i < 3; ++i) {
      float val = 0.f;
      int c = 48 + u * 3 + i;
      if (valid) { val = srow[c] * inv + narow[c]; dout[(size_t)n * 78 + c] = val; }
      qq += val * val;
    }
#pragma unroll
    for (int o = 16; o; o >>= 1) qq += __shfl_xor_sync(0xffffffffu, qq, o);
    if ((tid & 31) == 0) atomicAdd(&sP[96 + u], qq);
  }
  __syncthreads();
  if (tid < 106) atomicAdd(&g_stats[tid], sP[tid]);
}

// ---------------- K4: apply batch norm in place ----------------
__global__ void k_bn(const float* __restrict__ bnw, const float* __restrict__ bnb,
                     float* __restrict__ dout) {
  int idx = blockIdx.x * blockDim.x + threadIdx.x;
  if (idx >= NNODE * 78) return;
  int c = idx % 78;
  float x = dout[idx];
  if (c < 48) {
    float mean = g_stats[c] * (1.f / NNODE);
    float var  = g_stats[48 + c] * (1.f / NNODE) - mean * mean;
    dout[idx] = (x - mean) * rsqrtf(var + EPS_BN) * bnw[c] + bnb[c];
  } else {
    int u = (c - 48) / 3;
    float vn = g_stats[96 + u] * (1.f / (3.f * NNODE));
    dout[idx] = x * rsqrtf(vn + EPS_BN) * bnw[48 + u];
  }
}

// ---------------- launch ----------------
extern "C" void kernel_launch(void* const* d_in, const int* in_sizes, int n_in,
                              void* d_out, int out_size) {
  const float* node_attr  = (const float*)d_in[0];
  const int*   edge_index = (const int*)d_in[1];
  const float* edge_attr  = (const float*)d_in[2];
  const float* edge_sh    = (const float*)d_in[3];
  const float* fc_w1      = (const float*)d_in[4];
  const float* fc_b1      = (const float*)d_in[5];
  const float* fc_w2      = (const float*)d_in[6];
  const float* fc_b2      = (const float*)d_in[7];
  const float* bn_w       = (const float*)d_in[8];
  const float* bn_b       = (const float*)d_in[9];
  float* out = (float*)d_out;

  cudaFuncSetAttribute(k_gemm1, cudaFuncAttributeMaxDynamicSharedMemorySize, K1_SMEM);
  cudaFuncSetAttribute(k_fused, cudaFuncAttributeMaxDynamicSharedMemorySize, K2_SMEM);

  k_zero<<<256, 256>>>();
  k_prep<<<480, 512>>>(fc_w1, fc_w2);
  k_gemm1<<<NBLK, 256, K1_SMEM>>>(edge_attr, fc_b1);
  k_fused<<<NBLK, 256, K2_SMEM>>>(edge_index, node_attr, edge_sh, fc_b2);
  k_node<<<(NNODE + 255) / 256, 256>>>(node_attr, out);
  k_bn<<<(NNODE * 78 + 255) / 256, 256>>>(bn_w, bn_b, out);
}